// round 13
// baseline (speedup 1.0000x reference)
#include <cuda_runtime.h>
#include <cuda_bf16.h>
#include <math.h>

// ContextVAE, two-kernel pipeline (R13: g_msum stored in dec's A-fragment
// blocked layout -> dec's msum loads are perfectly coalesced):
//  K1 (msg): x1 @ W2^T on tensor cores (3xTF32 mma.m16n8k8), fragment-packed W2.
//  K2 (dec): msum @ W3^T on tensor cores (fragment-packed W3), x3 @ Wmv
//            in-fragment FFMA2 + shfl reduce; reparam + decoder scalar.
// g_msum layout: elem e, feature j stored at
//   (e>>4)*640 + (j>>2)*64 + ((e>>3)&1)*32 + (e&7)*4 + (j&3)

#define BATCH 262144
#define NT 256

typedef unsigned long long u64;
typedef unsigned int u32;

__device__ float g_msum[(size_t)BATCH * 40];   // 42MB scratch

__device__ __forceinline__ u64 f2fma(u64 a, u64 b, u64 c) {
    u64 d;
    asm("fma.rn.f32x2 %0, %1, %2, %3;" : "=l"(d) : "l"(a), "l"(b), "l"(c));
    return d;
}
__device__ __forceinline__ u64 f2add(u64 a, u64 b) {
    u64 d;
    asm("add.rn.f32x2 %0, %1, %2;" : "=l"(d) : "l"(a), "l"(b));
    return d;
}
__device__ __forceinline__ u64 f2pack(float lo, float hi) {
    u64 r;
    asm("mov.b64 %0, {%1, %2};" : "=l"(r) : "f"(lo), "f"(hi));
    return r;
}
__device__ __forceinline__ u64 f2dup(float v) {
    u64 r;
    asm("mov.b64 %0, {%1, %1};" : "=l"(r) : "f"(v));
    return r;
}
__device__ __forceinline__ float2 f2unpack(u64 p) {
    float2 r;
    asm("mov.b64 {%0, %1}, %2;" : "=f"(r.x), "=f"(r.y) : "l"(p));
    return r;
}
__device__ __forceinline__ u32 f2tf32(float x) {
    u32 r;
    asm("cvt.rna.tf32.f32 %0, %1;" : "=r"(r) : "f"(x));
    return r;
}
__device__ __forceinline__ void mma_tf32(float* d, const u32* a, const u32* b) {
    asm("mma.sync.aligned.m16n8k8.row.col.f32.tf32.tf32.f32 "
        "{%0,%1,%2,%3}, {%4,%5,%6,%7}, {%8,%9}, {%0,%1,%2,%3};"
        : "+f"(d[0]), "+f"(d[1]), "+f"(d[2]), "+f"(d[3])
        : "r"(a[0]), "r"(a[1]), "r"(a[2]), "r"(a[3]), "r"(b[0]), "r"(b[1]));
}

// ===================== K1: message stage =====================
#define OFF1_W1W  0
#define OFF1_W1B  (OFF1_W1W + 128*4)
#define OFF1_W2P  (OFF1_W1B + 128*4)
#define OFF1_B2   (OFF1_W2P + 16*5*32*4)
#define OFF1_CUR  (OFF1_B2 + 40)
#define SMEM1_FLOATS (OFF1_CUR + 256*12)
#define SMEM1_BYTES  (SMEM1_FLOATS * 4)

__global__ __launch_bounds__(NT, 2)
void msg_kernel(const float* __restrict__ current_c,
                const float* __restrict__ W1, const float* __restrict__ b1,
                const float* __restrict__ W2, const float* __restrict__ b2)
{
    extern __shared__ float sm[];
    float* sW1w = sm + OFF1_W1W;
    float* sW1b = sm + OFF1_W1B;
    float* sW2P = sm + OFF1_W2P;
    float* sB2  = sm + OFF1_B2;
    float* sCur = sm + OFF1_CUR;

    const int t = threadIdx.x;

    for (int o = t; o < 128; o += NT) {
        sW1w[o*4+0] = __ldg(&W1[o*13 + 10]);
        sW1w[o*4+1] = __ldg(&W1[o*13 + 11]);
        sW1w[o*4+2] = __ldg(&W1[o*13 + 12]);
        sW1w[o*4+3] = 0.f;
        float bb = __ldg(&b1[o]) + __ldg(&W1[o*13 + 0]);
        #pragma unroll
        for (int e = 0; e < 4; e++)
            sW1b[o*4+e] = bb + __ldg(&W1[o*13 + 6 + e]);
    }
    // fragment-packed W2
    for (int i = t; i < 16*5*32; i += NT) {
        int ks = i / 160;
        int r  = i % 160;
        int nt = r / 32;
        int lane = r % 32;
        int r0 = lane >> 2, cI = lane & 3;
        int n  = nt*8 + r0;          // W2 row j (output), 0..39
        int k0 = ks*8 + cI;
        int k4 = k0 + 4;
        float w0 = (n < 39) ? __ldg(&W2[n*128 + k0]) : 0.f;
        float w4 = (n < 39) ? __ldg(&W2[n*128 + k4]) : 0.f;
        float h0 = __uint_as_float(f2tf32(w0));
        float h4 = __uint_as_float(f2tf32(w4));
        float l0 = __uint_as_float(f2tf32(w0 - h0));
        float l4 = __uint_as_float(f2tf32(w4 - h4));
        ((float4*)sW2P)[i] = make_float4(h0, h4, l0, l4);
    }
    if (t < 40) sB2[t] = (t < 39) ? __ldg(&b2[t]) : 0.f;
    {
        const int b = blockIdx.x * NT + t;
        const float* cc = current_c + (size_t)b * 30;
        #pragma unroll
        for (int e = 0; e < 4; e++) {
            sCur[t*12 + 3*e + 0] = __ldg(&cc[e]);
            sCur[t*12 + 3*e + 1] = __ldg(&cc[10 + e]);
            sCur[t*12 + 3*e + 2] = __ldg(&cc[14 + 4*e]);
        }
    }
    __syncthreads();

    const int lane = t & 31;
    const int warp = t >> 5;
    const int r0   = lane >> 2;
    const int cIdx = lane & 3;
    const int edge = r0 & 3;
    const int blockElem0 = blockIdx.x * NT;

    #pragma unroll 1
    for (int pass = 0; pass < 4; pass++) {
        const int eb = warp*32 + pass*8;

        float p[2][2][3];
        #pragma unroll
        for (int mt = 0; mt < 2; mt++)
            #pragma unroll
            for (int h = 0; h < 2; h++) {
                int e = eb + mt*4 + (r0 >> 2) + 2*h;
                p[mt][h][0] = sCur[e*12 + edge*3 + 0];
                p[mt][h][1] = sCur[e*12 + edge*3 + 1];
                p[mt][h][2] = sCur[e*12 + edge*3 + 2];
            }

        float acc[2][5][4];
        #pragma unroll
        for (int mt = 0; mt < 2; mt++)
            #pragma unroll
            for (int nt = 0; nt < 5; nt++)
                #pragma unroll
                for (int i = 0; i < 4; i++) acc[mt][nt][i] = 0.f;

        #pragma unroll 1
        for (int ks = 0; ks < 16; ks++) {
            const int c0 = ks*8 + cIdx;
            const int c1 = c0 + 4;
            float4 w0 = ((const float4*)sW1w)[c0];
            float4 w1 = ((const float4*)sW1w)[c1];
            float bias0 = sW1b[c0*4 + edge];
            float bias1 = sW1b[c1*4 + edge];

            u32 bhi[5][2], blo[5][2];
            #pragma unroll
            for (int nt = 0; nt < 5; nt++) {
                float4 f = ((const float4*)sW2P)[(ks*5 + nt)*32 + lane];
                bhi[nt][0] = __float_as_uint(f.x);
                bhi[nt][1] = __float_as_uint(f.y);
                blo[nt][0] = __float_as_uint(f.z);
                blo[nt][1] = __float_as_uint(f.w);
            }

            #pragma unroll
            for (int mt = 0; mt < 2; mt++) {
                float x00 = fmaxf(fmaf(w0.x, p[mt][0][0], fmaf(w0.y, p[mt][0][1],
                                  fmaf(w0.z, p[mt][0][2], bias0))), 0.f);
                float x10 = fmaxf(fmaf(w0.x, p[mt][1][0], fmaf(w0.y, p[mt][1][1],
                                  fmaf(w0.z, p[mt][1][2], bias0))), 0.f);
                float x01 = fmaxf(fmaf(w1.x, p[mt][0][0], fmaf(w1.y, p[mt][0][1],
                                  fmaf(w1.z, p[mt][0][2], bias1))), 0.f);
                float x11 = fmaxf(fmaf(w1.x, p[mt][1][0], fmaf(w1.y, p[mt][1][1],
                                  fmaf(w1.z, p[mt][1][2], bias1))), 0.f);
                u32 ahi[4], alo[4];
                ahi[0] = f2tf32(x00); ahi[1] = f2tf32(x10);
                ahi[2] = f2tf32(x01); ahi[3] = f2tf32(x11);
                alo[0] = f2tf32(x00 - __uint_as_float(ahi[0]));
                alo[1] = f2tf32(x10 - __uint_as_float(ahi[1]));
                alo[2] = f2tf32(x01 - __uint_as_float(ahi[2]));
                alo[3] = f2tf32(x11 - __uint_as_float(ahi[3]));
                #pragma unroll
                for (int nt = 0; nt < 5; nt++) {
                    mma_tf32(acc[mt][nt], ahi, bhi[nt]);
                    mma_tf32(acc[mt][nt], ahi, blo[nt]);
                    mma_tf32(acc[mt][nt], alo, bhi[nt]);
                }
            }
        }

        // epilogue: +b2, relu, edge-sum via shfl, store in blocked layout
        const int grp  = (blockElem0 + eb) >> 4;          // 16-elem group
        const int ebit = (eb >> 3) & 1;                   // which 8-block in group
        #pragma unroll
        for (int mt = 0; mt < 2; mt++) {
            #pragma unroll
            for (int nt = 0; nt < 5; nt++) {
                int jb = nt*8 + cIdx*2;
                float2 b2v = *(const float2*)&sB2[jb];
                float v0 = fmaxf(acc[mt][nt][0] + b2v.x, 0.f);
                float v1 = fmaxf(acc[mt][nt][1] + b2v.y, 0.f);
                float v2 = fmaxf(acc[mt][nt][2] + b2v.x, 0.f);
                float v3 = fmaxf(acc[mt][nt][3] + b2v.y, 0.f);
                v0 += __shfl_xor_sync(0xffffffffu, v0, 4);
                v1 += __shfl_xor_sync(0xffffffffu, v1, 4);
                v2 += __shfl_xor_sync(0xffffffffu, v2, 4);
                v3 += __shfl_xor_sync(0xffffffffu, v3, 4);
                v0 += __shfl_xor_sync(0xffffffffu, v0, 8);
                v1 += __shfl_xor_sync(0xffffffffu, v1, 8);
                v2 += __shfl_xor_sync(0xffffffffu, v2, 8);
                v3 += __shfl_xor_sync(0xffffffffu, v3, 8);
                if (edge == 0) {
                    // elem offsets within 8-block: er and er+2
                    int er = mt*4 + (r0 >> 2);
                    int i4 = jb >> 2;          // = 2*nt + (cIdx>>1)
                    int c2 = jb & 3;           // = 2*(cIdx&1), float2-aligned
                    size_t base = (size_t)grp*640 + i4*64 + ebit*32 + c2;
                    *(float2*)&g_msum[base + er*4]       = make_float2(v0, v1);
                    *(float2*)&g_msum[base + (er+2)*4]   = make_float2(v2, v3);
                }
            }
        }
    }
}

// ===================== K2: readout on tensor cores + decoder ==================
#define OFF2_W3P  0
#define OFF2_WMVP (OFF2_W3P + 16*5*32*4)      // 10240
#define OFF2_WD1  (OFF2_WMVP + 16*4*9*4)      // 12544
#define OFF2_WD2  (OFF2_WD1 + 32*24)          // 13312
#define OFF2_BMV  (OFF2_WD2 + 32*12)          // 13696
#define OFF2_BD2  (OFF2_BMV + 16)             // 13712
#define OFF2_MV   (OFF2_BD2 + 16)             // 13728, 16B aligned
#define SMEM2_FLOATS (OFF2_MV + 256*20)
#define SMEM2_BYTES  (SMEM2_FLOATS * 4)

__global__ __launch_bounds__(NT, 2)
void dec_kernel(const float* __restrict__ initial_c,
                const float* __restrict__ eps,
                const float* __restrict__ W3, const float* __restrict__ b3,
                const float* __restrict__ Wm, const float* __restrict__ bm,
                const float* __restrict__ Wv, const float* __restrict__ bv,
                const float* __restrict__ Wd1, const float* __restrict__ bd1,
                const float* __restrict__ Wd2, const float* __restrict__ bd2,
                float* __restrict__ out)
{
    extern __shared__ float sm[];
    float* sW3P  = sm + OFF2_W3P;
    float* sWmvP = sm + OFF2_WMVP;
    float* sWd1  = sm + OFF2_WD1;
    float* sWd2  = sm + OFF2_WD2;
    float* sBmv  = sm + OFF2_BMV;
    float* sBd2  = sm + OFF2_BD2;
    float* sMV   = sm + OFF2_MV;

    const int t = threadIdx.x;

    // fragment-packed W3 (+ b3 at k=39)
    for (int i = t; i < 16*5*32; i += NT) {
        int ntG = i / 160;
        int r   = i % 160;
        int ks  = r / 32;
        int ln  = r % 32;
        int rr0 = ln >> 2, cI = ln & 3;
        int n  = ntG*8 + rr0;        // 0..127
        int k0 = ks*8 + cI;          // 0..35
        int k4 = k0 + 4;             // 4..39
        float w0 = __ldg(&W3[n*39 + k0]);
        float w4 = (k4 < 39) ? __ldg(&W3[n*39 + k4]) : __ldg(&b3[n]);
        float h0 = __uint_as_float(f2tf32(w0));
        float h4 = __uint_as_float(f2tf32(w4));
        float l0 = __uint_as_float(f2tf32(w0 - h0));
        float l4 = __uint_as_float(f2tf32(w4 - h4));
        ((float4*)sW3P)[i] = make_float4(h0, h4, l0, l4);
    }
    // bank-padded per-cIdx Wmv pack
    for (int i = t; i < 16*4*8; i += NT) {
        int ht = i / 32;
        int rr = i % 32;
        int cI = rr / 8;
        int q  = rr % 8;
        int j  = ht*8 + 2*cI + (q >> 2);
        int ch = q & 3;
        float v[4];
        #pragma unroll
        for (int c = 0; c < 4; c++) {
            int q16 = ch*4 + c;
            v[c] = (q16 < 8) ? __ldg(&Wm[q16*128 + j]) : __ldg(&Wv[(q16-8)*128 + j]);
        }
        ((float4*)(sWmvP + ((ht*4 + cI)*9 + q)*4))[0] = make_float4(v[0], v[1], v[2], v[3]);
    }
    for (int i = t; i < 32*24; i += NT) {
        int h = i / 24, q = i % 24;
        float v;
        if (q < 12)       v = __ldg(&Wd1[h*25 + 5 + q]);
        else if (q < 20)  v = __ldg(&Wd1[h*25 + 17 + (q-12)]);
        else if (q == 20) v = __ldg(&bd1[h]) + __ldg(&Wd1[h*25 + 0]);
        else              v = 0.f;
        sWd1[i] = v;
    }
    for (int i = t; i < 32*12; i += NT) {
        int h = i / 12, j = i % 12;
        sWd2[i] = __ldg(&Wd2[j*32 + h]);
    }
    if (t < 16) sBmv[t] = (t < 8) ? __ldg(&bm[t]) : __ldg(&bv[t-8]);
    if (t < 12) sBd2[t] = __ldg(&bd2[t]);
    __syncthreads();

    const int lane = t & 31;
    const int warp = t >> 5;
    const int r0   = lane >> 2;       // 0..7
    const int cIdx = lane & 3;        // 0..3
    const int warpE0 = blockIdx.x * NT + warp*32;
    const int locE0  = warp*32;

    #pragma unroll 1
    for (int pass = 0; pass < 2; pass++) {
        // blocked-layout msum load: fully coalesced (addr offset == lane)
        float msR0[10], msR8[10];
        {
            const int grp = (warpE0 + pass*16) >> 4;
            const float* gb = g_msum + (size_t)grp*640 + r0*4 + cIdx;
            #pragma unroll
            for (int i = 0; i < 10; i++) {
                msR0[i] = __ldg(&gb[i*64]);
                msR8[i] = __ldg(&gb[i*64 + 32]);
            }
        }
        if (cIdx == 3) { msR0[9] = 1.0f; msR8[9] = 1.0f; }  // bias column k=39

        u64 pA[8], pB[8];
        #pragma unroll
        for (int q = 0; q < 8; q++) { pA[q] = 0ULL; pB[q] = 0ULL; }

        #pragma unroll 1
        for (int half = 0; half < 2; half++) {
            float acc[8][4];
            #pragma unroll
            for (int nt = 0; nt < 8; nt++)
                #pragma unroll
                for (int i = 0; i < 4; i++) acc[nt][i] = 0.f;

            #pragma unroll
            for (int ks = 0; ks < 5; ks++) {
                u32 ahi[4], alo[4];
                {
                    float a0 = msR0[2*ks], a1 = msR8[2*ks];
                    float a2 = msR0[2*ks+1], a3 = msR8[2*ks+1];
                    ahi[0] = f2tf32(a0); ahi[1] = f2tf32(a1);
                    ahi[2] = f2tf32(a2); ahi[3] = f2tf32(a3);
                    alo[0] = f2tf32(a0 - __uint_as_float(ahi[0]));
                    alo[1] = f2tf32(a1 - __uint_as_float(ahi[1]));
                    alo[2] = f2tf32(a2 - __uint_as_float(ahi[2]));
                    alo[3] = f2tf32(a3 - __uint_as_float(ahi[3]));
                }
                #pragma unroll
                for (int nt = 0; nt < 8; nt++) {
                    float4 f = ((const float4*)sW3P)[((half*8 + nt)*5 + ks)*32 + lane];
                    u32 bhi[2] = {__float_as_uint(f.x), __float_as_uint(f.y)};
                    u32 blo[2] = {__float_as_uint(f.z), __float_as_uint(f.w)};
                    mma_tf32(acc[nt], ahi, bhi);
                    mma_tf32(acc[nt], ahi, blo);
                    mma_tf32(acc[nt], alo, bhi);
                }
            }

            // fold x3 (this 64-col half) into mv partials
            #pragma unroll
            for (int nt = 0; nt < 8; nt++) {
                int ht = half*8 + nt;
                const ulonglong2* wp = (const ulonglong2*)(sWmvP + ((ht*4 + cIdx)*9)*4);
                float xA0 = fmaxf(acc[nt][0], 0.f);
                float xA1 = fmaxf(acc[nt][1], 0.f);
                float xB0 = fmaxf(acc[nt][2], 0.f);
                float xB1 = fmaxf(acc[nt][3], 0.f);
                u64 dA0 = f2dup(xA0), dA1 = f2dup(xA1);
                u64 dB0 = f2dup(xB0), dB1 = f2dup(xB1);
                #pragma unroll
                for (int q = 0; q < 4; q++) {
                    ulonglong2 c0v = wp[q];      // row j0 chunk q
                    ulonglong2 c1v = wp[4 + q];  // row j0+1 chunk q
                    pA[2*q]   = f2fma(c0v.x, dA0, pA[2*q]);
                    pA[2*q+1] = f2fma(c0v.y, dA0, pA[2*q+1]);
                    pA[2*q]   = f2fma(c1v.x, dA1, pA[2*q]);
                    pA[2*q+1] = f2fma(c1v.y, dA1, pA[2*q+1]);
                    pB[2*q]   = f2fma(c0v.x, dB0, pB[2*q]);
                    pB[2*q+1] = f2fma(c0v.y, dB0, pB[2*q+1]);
                    pB[2*q]   = f2fma(c1v.x, dB1, pB[2*q]);
                    pB[2*q+1] = f2fma(c1v.y, dB1, pB[2*q+1]);
                }
            }
        }

        // reduce partials across the 4 cIdx lanes
        #pragma unroll
        for (int q = 0; q < 8; q++) {
            pA[q] = f2add(pA[q], __shfl_xor_sync(0xffffffffu, pA[q], 1));
            pB[q] = f2add(pB[q], __shfl_xor_sync(0xffffffffu, pB[q], 1));
            pA[q] = f2add(pA[q], __shfl_xor_sync(0xffffffffu, pA[q], 2));
            pB[q] = f2add(pB[q], __shfl_xor_sync(0xffffffffu, pB[q], 2));
        }
        {
            int eA = locE0 + pass*16 + r0;
            int eB = eA + 8;
            float4 bq = *(const float4*)&sBmv[4*cIdx];
            float2 a0 = f2unpack(pA[2*cIdx]);
            float2 a1 = f2unpack(pA[2*cIdx+1]);
            float2 b0 = f2unpack(pB[2*cIdx]);
            float2 b1 = f2unpack(pB[2*cIdx+1]);
            *(float4*)&sMV[eA*20 + 4*cIdx] =
                make_float4(a0.x + bq.x, a0.y + bq.y, a1.x + bq.z, a1.y + bq.w);
            *(float4*)&sMV[eB*20 + 4*cIdx] =
                make_float4(b0.x + bq.x, b0.y + bq.y, b1.x + bq.z, b1.y + bq.w);
        }
    }
    __syncwarp();

    // ======== reparam + decoder: 1 element/thread ========
    const int b = blockIdx.x * NT + t;
    float mvs[16];
    {
        const float4* mvp = (const float4*)&sMV[t*20];
        #pragma unroll
        for (int q = 0; q < 4; q++) {
            float4 v = mvp[q];
            mvs[4*q+0] = v.x; mvs[4*q+1] = v.y; mvs[4*q+2] = v.z; mvs[4*q+3] = v.w;
        }
    }

    const float4* epv = (const float4*)(eps + (size_t)b * 8);
    float4 e0 = epv[0], e1 = epv[1];
    float ev[8] = {e0.x, e0.y, e0.z, e0.w, e1.x, e1.y, e1.z, e1.w};
    float zv[8];
    #pragma unroll
    for (int i = 0; i < 8; i++)
        zv[i] = fmaf(ev[i], __expf(0.5f * mvs[8+i]), mvs[i]);

    const float* ic = initial_c + (size_t)b * 30;
    u64 d2[12];
    d2[0] = f2pack(__ldg(&ic[0]),  __ldg(&ic[1]));
    d2[1] = f2pack(__ldg(&ic[2]),  __ldg(&ic[3]));
    d2[2] = f2pack(__ldg(&ic[10]), __ldg(&ic[11]));
    d2[3] = f2pack(__ldg(&ic[12]), __ldg(&ic[13]));
    d2[4] = f2pack(__ldg(&ic[14]), __ldg(&ic[18]));
    d2[5] = f2pack(__ldg(&ic[22]), __ldg(&ic[26]));
    d2[6] = f2pack(zv[0], zv[1]);
    d2[7] = f2pack(zv[2], zv[3]);
    d2[8] = f2pack(zv[4], zv[5]);
    d2[9] = f2pack(zv[6], zv[7]);
    d2[10] = f2pack(1.f, 0.f);
    d2[11] = 0ULL;

    u64 r2[6];
    {
        const ulonglong2* bb = (const ulonglong2*)sBd2;
        #pragma unroll
        for (int q = 0; q < 3; q++) {
            ulonglong2 v = bb[q];
            r2[2*q] = v.x; r2[2*q+1] = v.y;
        }
    }

    #pragma unroll 4
    for (int h = 0; h < 32; h++) {
        const ulonglong2* w1r = (const ulonglong2*)(sWd1 + h*24);
        u64 t0 = 0ULL, t1 = 0ULL, t2 = 0ULL, t3 = 0ULL;
        #pragma unroll
        for (int q = 0; q < 6; q += 2) {
            ulonglong2 cc0 = w1r[q];
            ulonglong2 cc1 = w1r[q+1];
            t0 = f2fma(cc0.x, d2[2*q],   t0);
            t1 = f2fma(cc0.y, d2[2*q+1], t1);
            t2 = f2fma(cc1.x, d2[2*q+2], t2);
            t3 = f2fma(cc1.y, d2[2*q+3], t3);
        }
        u64 st = f2add(f2add(t0, t2), f2add(t1, t3));
        float2 u = f2unpack(st);
        float hv = fmaxf(u.x + u.y, 0.f);
        u64 hp = f2dup(hv);
        const ulonglong2* w2r = (const ulonglong2*)(sWd2 + h*12);
        #pragma unroll
        for (int q = 0; q < 3; q++) {
            ulonglong2 c = w2r[q];
            r2[2*q]   = f2fma(c.x, hp, r2[2*q]);
            r2[2*q+1] = f2fma(c.y, hp, r2[2*q+1]);
        }
    }

    float rr[12];
    #pragma unroll
    for (int q = 0; q < 6; q++) {
        float2 v = f2unpack(r2[q]);
        rr[2*q] = v.x; rr[2*q+1] = v.y;
    }
    float* out_rec = out + (size_t)b * 12;
    #pragma unroll
    for (int ii = 0; ii < 3; ii++) {
        float4 v;
        v.x = __fdividef(1.f, 1.f + __expf(-rr[ii*4+0]));
        v.y = __fdividef(1.f, 1.f + __expf(-rr[ii*4+1]));
        v.z = __fdividef(1.f, 1.f + __expf(-rr[ii*4+2]));
        v.w = __fdividef(1.f, 1.f + __expf(-rr[ii*4+3]));
        ((float4*)out_rec)[ii] = v;
    }
    float* out_mean = out + (size_t)12*BATCH + (size_t)b*8;
    ((float4*)out_mean)[0] = make_float4(mvs[0], mvs[1], mvs[2], mvs[3]);
    ((float4*)out_mean)[1] = make_float4(mvs[4], mvs[5], mvs[6], mvs[7]);
    float* out_lv = out + (size_t)20*BATCH + (size_t)b*8;
    ((float4*)out_lv)[0] = make_float4(mvs[8],  mvs[9],  mvs[10], mvs[11]);
    ((float4*)out_lv)[1] = make_float4(mvs[12], mvs[13], mvs[14], mvs[15]);
    float* out_z = out + (size_t)28*BATCH + (size_t)b*8;
    ((float4*)out_z)[0] = make_float4(zv[0], zv[1], zv[2], zv[3]);
    ((float4*)out_z)[1] = make_float4(zv[4], zv[5], zv[6], zv[7]);
}

extern "C" void kernel_launch(void* const* d_in, const int* in_sizes, int n_in,
                              void* d_out, int out_size)
{
    const float* initial_c = (const float*)d_in[0];
    // d_in[1] = initial_s (unused)
    const float* current_c = (const float*)d_in[2];
    const float* eps       = (const float*)d_in[3];
    const float* W1  = (const float*)d_in[4];
    const float* b1  = (const float*)d_in[5];
    const float* W2  = (const float*)d_in[6];
    const float* b2  = (const float*)d_in[7];
    const float* W3  = (const float*)d_in[8];
    const float* b3  = (const float*)d_in[9];
    const float* Wm  = (const float*)d_in[10];
    const float* bm  = (const float*)d_in[11];
    const float* Wv  = (const float*)d_in[12];
    const float* bv  = (const float*)d_in[13];
    const float* Wd1 = (const float*)d_in[14];
    const float* bd1 = (const float*)d_in[15];
    const float* Wd2 = (const float*)d_in[16];
    const float* bd2 = (const float*)d_in[17];
    float* out = (float*)d_out;

    cudaFuncSetAttribute(msg_kernel, cudaFuncAttributeMaxDynamicSharedMemorySize, SMEM1_BYTES);
    cudaFuncSetAttribute(dec_kernel, cudaFuncAttributeMaxDynamicSharedMemorySize, SMEM2_BYTES);

    msg_kernel<<<BATCH / NT, NT, SMEM1_BYTES>>>(current_c, W1, b1, W2, b2);
    dec_kernel<<<BATCH / NT, NT, SMEM2_BYTES>>>(initial_c, eps,
        W3, b3, Wm, bm, Wv, bv, Wd1, bd1, Wd2, bd2, out);
}

// round 14
// speedup vs baseline: 1.5572x; 1.5572x over previous
#include <cuda_runtime.h>
#include <cuda_bf16.h>
#include <math.h>

// ContextVAE, two-kernel pipeline (R14 = R12 + dec-side warp-private msum
// staging; g_msum row layout and msg_kernel identical to R12):
//  K1 (msg): x1 @ W2^T on tensor cores (3xTF32 mma.m16n8k8), fragment-packed W2.
//  K2 (dec): per-pass coalesced bulk-load of msum rows into padded smem,
//            msum @ W3^T on tensor cores (fragment-packed W3), x3 @ Wmv
//            in-fragment FFMA2 + shfl reduce; reparam + decoder scalar.

#define BATCH 262144
#define NT 256

typedef unsigned long long u64;
typedef unsigned int u32;

__device__ float g_msum[(size_t)BATCH * 40];   // 42MB scratch (row layout)

__device__ __forceinline__ u64 f2fma(u64 a, u64 b, u64 c) {
    u64 d;
    asm("fma.rn.f32x2 %0, %1, %2, %3;" : "=l"(d) : "l"(a), "l"(b), "l"(c));
    return d;
}
__device__ __forceinline__ u64 f2add(u64 a, u64 b) {
    u64 d;
    asm("add.rn.f32x2 %0, %1, %2;" : "=l"(d) : "l"(a), "l"(b));
    return d;
}
__device__ __forceinline__ u64 f2pack(float lo, float hi) {
    u64 r;
    asm("mov.b64 %0, {%1, %2};" : "=l"(r) : "f"(lo), "f"(hi));
    return r;
}
__device__ __forceinline__ u64 f2dup(float v) {
    u64 r;
    asm("mov.b64 %0, {%1, %1};" : "=l"(r) : "f"(v));
    return r;
}
__device__ __forceinline__ float2 f2unpack(u64 p) {
    float2 r;
    asm("mov.b64 {%0, %1}, %2;" : "=f"(r.x), "=f"(r.y) : "l"(p));
    return r;
}
__device__ __forceinline__ u32 f2tf32(float x) {
    u32 r;
    asm("cvt.rna.tf32.f32 %0, %1;" : "=r"(r) : "f"(x));
    return r;
}
__device__ __forceinline__ void mma_tf32(float* d, const u32* a, const u32* b) {
    asm("mma.sync.aligned.m16n8k8.row.col.f32.tf32.tf32.f32 "
        "{%0,%1,%2,%3}, {%4,%5,%6,%7}, {%8,%9}, {%0,%1,%2,%3};"
        : "+f"(d[0]), "+f"(d[1]), "+f"(d[2]), "+f"(d[3])
        : "r"(a[0]), "r"(a[1]), "r"(a[2]), "r"(a[3]), "r"(b[0]), "r"(b[1]));
}

// ===================== K1: message stage (identical to R12) =====================
#define OFF1_W1W  0
#define OFF1_W1B  (OFF1_W1W + 128*4)
#define OFF1_W2P  (OFF1_W1B + 128*4)
#define OFF1_B2   (OFF1_W2P + 16*5*32*4)
#define OFF1_CUR  (OFF1_B2 + 40)
#define SMEM1_FLOATS (OFF1_CUR + 256*12)
#define SMEM1_BYTES  (SMEM1_FLOATS * 4)

__global__ __launch_bounds__(NT, 2)
void msg_kernel(const float* __restrict__ current_c,
                const float* __restrict__ W1, const float* __restrict__ b1,
                const float* __restrict__ W2, const float* __restrict__ b2)
{
    extern __shared__ float sm[];
    float* sW1w = sm + OFF1_W1W;
    float* sW1b = sm + OFF1_W1B;
    float* sW2P = sm + OFF1_W2P;
    float* sB2  = sm + OFF1_B2;
    float* sCur = sm + OFF1_CUR;

    const int t = threadIdx.x;

    for (int o = t; o < 128; o += NT) {
        sW1w[o*4+0] = __ldg(&W1[o*13 + 10]);
        sW1w[o*4+1] = __ldg(&W1[o*13 + 11]);
        sW1w[o*4+2] = __ldg(&W1[o*13 + 12]);
        sW1w[o*4+3] = 0.f;
        float bb = __ldg(&b1[o]) + __ldg(&W1[o*13 + 0]);
        #pragma unroll
        for (int e = 0; e < 4; e++)
            sW1b[o*4+e] = bb + __ldg(&W1[o*13 + 6 + e]);
    }
    // fragment-packed W2
    for (int i = t; i < 16*5*32; i += NT) {
        int ks = i / 160;
        int r  = i % 160;
        int nt = r / 32;
        int lane = r % 32;
        int r0 = lane >> 2, cI = lane & 3;
        int n  = nt*8 + r0;
        int k0 = ks*8 + cI;
        int k4 = k0 + 4;
        float w0 = (n < 39) ? __ldg(&W2[n*128 + k0]) : 0.f;
        float w4 = (n < 39) ? __ldg(&W2[n*128 + k4]) : 0.f;
        float h0 = __uint_as_float(f2tf32(w0));
        float h4 = __uint_as_float(f2tf32(w4));
        float l0 = __uint_as_float(f2tf32(w0 - h0));
        float l4 = __uint_as_float(f2tf32(w4 - h4));
        ((float4*)sW2P)[i] = make_float4(h0, h4, l0, l4);
    }
    if (t < 40) sB2[t] = (t < 39) ? __ldg(&b2[t]) : 0.f;
    {
        const int b = blockIdx.x * NT + t;
        const float* cc = current_c + (size_t)b * 30;
        #pragma unroll
        for (int e = 0; e < 4; e++) {
            sCur[t*12 + 3*e + 0] = __ldg(&cc[e]);
            sCur[t*12 + 3*e + 1] = __ldg(&cc[10 + e]);
            sCur[t*12 + 3*e + 2] = __ldg(&cc[14 + 4*e]);
        }
    }
    __syncthreads();

    const int lane = t & 31;
    const int warp = t >> 5;
    const int r0   = lane >> 2;
    const int cIdx = lane & 3;
    const int edge = r0 & 3;
    const int blockElem0 = blockIdx.x * NT;

    #pragma unroll 1
    for (int pass = 0; pass < 4; pass++) {
        const int eb = warp*32 + pass*8;

        float p[2][2][3];
        #pragma unroll
        for (int mt = 0; mt < 2; mt++)
            #pragma unroll
            for (int h = 0; h < 2; h++) {
                int e = eb + mt*4 + (r0 >> 2) + 2*h;
                p[mt][h][0] = sCur[e*12 + edge*3 + 0];
                p[mt][h][1] = sCur[e*12 + edge*3 + 1];
                p[mt][h][2] = sCur[e*12 + edge*3 + 2];
            }

        float acc[2][5][4];
        #pragma unroll
        for (int mt = 0; mt < 2; mt++)
            #pragma unroll
            for (int nt = 0; nt < 5; nt++)
                #pragma unroll
                for (int i = 0; i < 4; i++) acc[mt][nt][i] = 0.f;

        #pragma unroll 1
        for (int ks = 0; ks < 16; ks++) {
            const int c0 = ks*8 + cIdx;
            const int c1 = c0 + 4;
            float4 w0 = ((const float4*)sW1w)[c0];
            float4 w1 = ((const float4*)sW1w)[c1];
            float bias0 = sW1b[c0*4 + edge];
            float bias1 = sW1b[c1*4 + edge];

            u32 bhi[5][2], blo[5][2];
            #pragma unroll
            for (int nt = 0; nt < 5; nt++) {
                float4 f = ((const float4*)sW2P)[(ks*5 + nt)*32 + lane];
                bhi[nt][0] = __float_as_uint(f.x);
                bhi[nt][1] = __float_as_uint(f.y);
                blo[nt][0] = __float_as_uint(f.z);
                blo[nt][1] = __float_as_uint(f.w);
            }

            #pragma unroll
            for (int mt = 0; mt < 2; mt++) {
                float x00 = fmaxf(fmaf(w0.x, p[mt][0][0], fmaf(w0.y, p[mt][0][1],
                                  fmaf(w0.z, p[mt][0][2], bias0))), 0.f);
                float x10 = fmaxf(fmaf(w0.x, p[mt][1][0], fmaf(w0.y, p[mt][1][1],
                                  fmaf(w0.z, p[mt][1][2], bias0))), 0.f);
                float x01 = fmaxf(fmaf(w1.x, p[mt][0][0], fmaf(w1.y, p[mt][0][1],
                                  fmaf(w1.z, p[mt][0][2], bias1))), 0.f);
                float x11 = fmaxf(fmaf(w1.x, p[mt][1][0], fmaf(w1.y, p[mt][1][1],
                                  fmaf(w1.z, p[mt][1][2], bias1))), 0.f);
                u32 ahi[4], alo[4];
                ahi[0] = f2tf32(x00); ahi[1] = f2tf32(x10);
                ahi[2] = f2tf32(x01); ahi[3] = f2tf32(x11);
                alo[0] = f2tf32(x00 - __uint_as_float(ahi[0]));
                alo[1] = f2tf32(x10 - __uint_as_float(ahi[1]));
                alo[2] = f2tf32(x01 - __uint_as_float(ahi[2]));
                alo[3] = f2tf32(x11 - __uint_as_float(ahi[3]));
                #pragma unroll
                for (int nt = 0; nt < 5; nt++) {
                    mma_tf32(acc[mt][nt], ahi, bhi[nt]);
                    mma_tf32(acc[mt][nt], ahi, blo[nt]);
                    mma_tf32(acc[mt][nt], alo, bhi[nt]);
                }
            }
        }

        #pragma unroll
        for (int mt = 0; mt < 2; mt++) {
            #pragma unroll
            for (int nt = 0; nt < 5; nt++) {
                int jb = nt*8 + cIdx*2;
                float2 b2v = *(const float2*)&sB2[jb];
                float v0 = fmaxf(acc[mt][nt][0] + b2v.x, 0.f);
                float v1 = fmaxf(acc[mt][nt][1] + b2v.y, 0.f);
                float v2 = fmaxf(acc[mt][nt][2] + b2v.x, 0.f);
                float v3 = fmaxf(acc[mt][nt][3] + b2v.y, 0.f);
                v0 += __shfl_xor_sync(0xffffffffu, v0, 4);
                v1 += __shfl_xor_sync(0xffffffffu, v1, 4);
                v2 += __shfl_xor_sync(0xffffffffu, v2, 4);
                v3 += __shfl_xor_sync(0xffffffffu, v3, 4);
                v0 += __shfl_xor_sync(0xffffffffu, v0, 8);
                v1 += __shfl_xor_sync(0xffffffffu, v1, 8);
                v2 += __shfl_xor_sync(0xffffffffu, v2, 8);
                v3 += __shfl_xor_sync(0xffffffffu, v3, 8);
                if (edge == 0) {
                    int eLo = blockElem0 + eb + mt*4 + (r0 >> 2);
                    *(float2*)&g_msum[(size_t)eLo*40 + jb]     = make_float2(v0, v1);
                    *(float2*)&g_msum[(size_t)(eLo+2)*40 + jb] = make_float2(v2, v3);
                }
            }
        }
    }
}

// ===================== K2: readout on tensor cores + decoder ==================
#define OFF2_W3P  0
#define OFF2_WMVP (OFF2_W3P + 16*5*32*4)      // 10240
#define OFF2_WD1  (OFF2_WMVP + 16*4*9*4)      // 12544
#define OFF2_WD2  (OFF2_WD1 + 32*24)          // 13312
#define OFF2_BMV  (OFF2_WD2 + 32*12)          // 13696
#define OFF2_BD2  (OFF2_BMV + 16)             // 13712
#define OFF2_MV   (OFF2_BD2 + 16)             // 13728, 16B aligned
#define OFF2_MS   (OFF2_MV + 256*20)          // 18848, warp-private msum stage
#define MS_STRIDE 44                          // floats per row (bank-padded)
#define SMEM2_FLOATS (OFF2_MS + 8*16*MS_STRIDE)
#define SMEM2_BYTES  (SMEM2_FLOATS * 4)

__global__ __launch_bounds__(NT, 2)
void dec_kernel(const float* __restrict__ initial_c,
                const float* __restrict__ eps,
                const float* __restrict__ W3, const float* __restrict__ b3,
                const float* __restrict__ Wm, const float* __restrict__ bm,
                const float* __restrict__ Wv, const float* __restrict__ bv,
                const float* __restrict__ Wd1, const float* __restrict__ bd1,
                const float* __restrict__ Wd2, const float* __restrict__ bd2,
                float* __restrict__ out)
{
    extern __shared__ float sm[];
    float* sW3P  = sm + OFF2_W3P;
    float* sWmvP = sm + OFF2_WMVP;
    float* sWd1  = sm + OFF2_WD1;
    float* sWd2  = sm + OFF2_WD2;
    float* sBmv  = sm + OFF2_BMV;
    float* sBd2  = sm + OFF2_BD2;
    float* sMV   = sm + OFF2_MV;

    const int t = threadIdx.x;

    // fragment-packed W3 (+ b3 at k=39)
    for (int i = t; i < 16*5*32; i += NT) {
        int ntG = i / 160;
        int r   = i % 160;
        int ks  = r / 32;
        int ln  = r % 32;
        int rr0 = ln >> 2, cI = ln & 3;
        int n  = ntG*8 + rr0;
        int k0 = ks*8 + cI;
        int k4 = k0 + 4;
        float w0 = __ldg(&W3[n*39 + k0]);
        float w4 = (k4 < 39) ? __ldg(&W3[n*39 + k4]) : __ldg(&b3[n]);
        float h0 = __uint_as_float(f2tf32(w0));
        float h4 = __uint_as_float(f2tf32(w4));
        float l0 = __uint_as_float(f2tf32(w0 - h0));
        float l4 = __uint_as_float(f2tf32(w4 - h4));
        ((float4*)sW3P)[i] = make_float4(h0, h4, l0, l4);
    }
    // bank-padded per-cIdx Wmv pack
    for (int i = t; i < 16*4*8; i += NT) {
        int ht = i / 32;
        int rr = i % 32;
        int cI = rr / 8;
        int q  = rr % 8;
        int j  = ht*8 + 2*cI + (q >> 2);
        int ch = q & 3;
        float v[4];
        #pragma unroll
        for (int c = 0; c < 4; c++) {
            int q16 = ch*4 + c;
            v[c] = (q16 < 8) ? __ldg(&Wm[q16*128 + j]) : __ldg(&Wv[(q16-8)*128 + j]);
        }
        ((float4*)(sWmvP + ((ht*4 + cI)*9 + q)*4))[0] = make_float4(v[0], v[1], v[2], v[3]);
    }
    for (int i = t; i < 32*24; i += NT) {
        int h = i / 24, q = i % 24;
        float v;
        if (q < 12)       v = __ldg(&Wd1[h*25 + 5 + q]);
        else if (q < 20)  v = __ldg(&Wd1[h*25 + 17 + (q-12)]);
        else if (q == 20) v = __ldg(&bd1[h]) + __ldg(&Wd1[h*25 + 0]);
        else              v = 0.f;
        sWd1[i] = v;
    }
    for (int i = t; i < 32*12; i += NT) {
        int h = i / 12, j = i % 12;
        sWd2[i] = __ldg(&Wd2[j*32 + h]);
    }
    if (t < 16) sBmv[t] = (t < 8) ? __ldg(&bm[t]) : __ldg(&bv[t-8]);
    if (t < 12) sBd2[t] = __ldg(&bd2[t]);
    __syncthreads();

    const int lane = t & 31;
    const int warp = t >> 5;
    const int r0   = lane >> 2;       // 0..7
    const int cIdx = lane & 3;        // 0..3
    const int warpE0 = blockIdx.x * NT + warp*32;
    const int locE0  = warp*32;
    float* sMSw = sm + OFF2_MS + warp * 16 * MS_STRIDE;   // warp-private

    #pragma unroll 1
    for (int pass = 0; pass < 2; pass++) {
        // ---- warp-private staging: 16 rows x 40 floats, coalesced LDG.128 ----
        __syncwarp();
        {
            const float4* src = (const float4*)(g_msum + (size_t)(warpE0 + pass*16) * 40);
            #pragma unroll
            for (int it = 0; it < 5; it++) {
                int idx = it*32 + lane;          // 0..159 float4s
                float4 v = __ldg(&src[idx]);
                int e = idx / 10, c = idx % 10;
                *(float4*)&sMSw[e*MS_STRIDE + c*4] = v;
            }
        }
        __syncwarp();

        // A-fragment reads: conflict-free scalar LDS
        float msR0[10], msR8[10];
        #pragma unroll
        for (int i = 0; i < 10; i++) {
            msR0[i] = sMSw[r0*MS_STRIDE + cIdx + 4*i];
            msR8[i] = sMSw[(r0+8)*MS_STRIDE + cIdx + 4*i];
        }
        if (cIdx == 3) { msR0[9] = 1.0f; msR8[9] = 1.0f; }  // bias column k=39

        u64 pA[8], pB[8];
        #pragma unroll
        for (int q = 0; q < 8; q++) { pA[q] = 0ULL; pB[q] = 0ULL; }

        #pragma unroll 1
        for (int half = 0; half < 2; half++) {
            float acc[8][4];
            #pragma unroll
            for (int nt = 0; nt < 8; nt++)
                #pragma unroll
                for (int i = 0; i < 4; i++) acc[nt][i] = 0.f;

            #pragma unroll
            for (int ks = 0; ks < 5; ks++) {
                u32 ahi[4], alo[4];
                {
                    float a0 = msR0[2*ks], a1 = msR8[2*ks];
                    float a2 = msR0[2*ks+1], a3 = msR8[2*ks+1];
                    ahi[0] = f2tf32(a0); ahi[1] = f2tf32(a1);
                    ahi[2] = f2tf32(a2); ahi[3] = f2tf32(a3);
                    alo[0] = f2tf32(a0 - __uint_as_float(ahi[0]));
                    alo[1] = f2tf32(a1 - __uint_as_float(ahi[1]));
                    alo[2] = f2tf32(a2 - __uint_as_float(ahi[2]));
                    alo[3] = f2tf32(a3 - __uint_as_float(ahi[3]));
                }
                #pragma unroll
                for (int nt = 0; nt < 8; nt++) {
                    float4 f = ((const float4*)sW3P)[((half*8 + nt)*5 + ks)*32 + lane];
                    u32 bhi[2] = {__float_as_uint(f.x), __float_as_uint(f.y)};
                    u32 blo[2] = {__float_as_uint(f.z), __float_as_uint(f.w)};
                    mma_tf32(acc[nt], ahi, bhi);
                    mma_tf32(acc[nt], ahi, blo);
                    mma_tf32(acc[nt], alo, bhi);
                }
            }

            // fold x3 (this 64-col half) into mv partials
            #pragma unroll
            for (int nt = 0; nt < 8; nt++) {
                int ht = half*8 + nt;
                const ulonglong2* wp = (const ulonglong2*)(sWmvP + ((ht*4 + cIdx)*9)*4);
                float xA0 = fmaxf(acc[nt][0], 0.f);
                float xA1 = fmaxf(acc[nt][1], 0.f);
                float xB0 = fmaxf(acc[nt][2], 0.f);
                float xB1 = fmaxf(acc[nt][3], 0.f);
                u64 dA0 = f2dup(xA0), dA1 = f2dup(xA1);
                u64 dB0 = f2dup(xB0), dB1 = f2dup(xB1);
                #pragma unroll
                for (int q = 0; q < 4; q++) {
                    ulonglong2 c0v = wp[q];
                    ulonglong2 c1v = wp[4 + q];
                    pA[2*q]   = f2fma(c0v.x, dA0, pA[2*q]);
                    pA[2*q+1] = f2fma(c0v.y, dA0, pA[2*q+1]);
                    pA[2*q]   = f2fma(c1v.x, dA1, pA[2*q]);
                    pA[2*q+1] = f2fma(c1v.y, dA1, pA[2*q+1]);
                    pB[2*q]   = f2fma(c0v.x, dB0, pB[2*q]);
                    pB[2*q+1] = f2fma(c0v.y, dB0, pB[2*q+1]);
                    pB[2*q]   = f2fma(c1v.x, dB1, pB[2*q]);
                    pB[2*q+1] = f2fma(c1v.y, dB1, pB[2*q+1]);
                }
            }
        }

        // reduce partials across the 4 cIdx lanes
        #pragma unroll
        for (int q = 0; q < 8; q++) {
            pA[q] = f2add(pA[q], __shfl_xor_sync(0xffffffffu, pA[q], 1));
            pB[q] = f2add(pB[q], __shfl_xor_sync(0xffffffffu, pB[q], 1));
            pA[q] = f2add(pA[q], __shfl_xor_sync(0xffffffffu, pA[q], 2));
            pB[q] = f2add(pB[q], __shfl_xor_sync(0xffffffffu, pB[q], 2));
        }
        {
            int eA = locE0 + pass*16 + r0;
            int eB = eA + 8;
            float4 bq = *(const float4*)&sBmv[4*cIdx];
            float2 a0 = f2unpack(pA[2*cIdx]);
            float2 a1 = f2unpack(pA[2*cIdx+1]);
            float2 b0 = f2unpack(pB[2*cIdx]);
            float2 b1 = f2unpack(pB[2*cIdx+1]);
            *(float4*)&sMV[eA*20 + 4*cIdx] =
                make_float4(a0.x + bq.x, a0.y + bq.y, a1.x + bq.z, a1.y + bq.w);
            *(float4*)&sMV[eB*20 + 4*cIdx] =
                make_float4(b0.x + bq.x, b0.y + bq.y, b1.x + bq.z, b1.y + bq.w);
        }
    }
    __syncwarp();

    // ======== reparam + decoder: 1 element/thread ========
    const int b = blockIdx.x * NT + t;
    float mvs[16];
    {
        const float4* mvp = (const float4*)&sMV[t*20];
        #pragma unroll
        for (int q = 0; q < 4; q++) {
            float4 v = mvp[q];
            mvs[4*q+0] = v.x; mvs[4*q+1] = v.y; mvs[4*q+2] = v.z; mvs[4*q+3] = v.w;
        }
    }

    const float4* epv = (const float4*)(eps + (size_t)b * 8);
    float4 e0 = epv[0], e1 = epv[1];
    float ev[8] = {e0.x, e0.y, e0.z, e0.w, e1.x, e1.y, e1.z, e1.w};
    float zv[8];
    #pragma unroll
    for (int i = 0; i < 8; i++)
        zv[i] = fmaf(ev[i], __expf(0.5f * mvs[8+i]), mvs[i]);

    const float* ic = initial_c + (size_t)b * 30;
    u64 d2[12];
    d2[0] = f2pack(__ldg(&ic[0]),  __ldg(&ic[1]));
    d2[1] = f2pack(__ldg(&ic[2]),  __ldg(&ic[3]));
    d2[2] = f2pack(__ldg(&ic[10]), __ldg(&ic[11]));
    d2[3] = f2pack(__ldg(&ic[12]), __ldg(&ic[13]));
    d2[4] = f2pack(__ldg(&ic[14]), __ldg(&ic[18]));
    d2[5] = f2pack(__ldg(&ic[22]), __ldg(&ic[26]));
    d2[6] = f2pack(zv[0], zv[1]);
    d2[7] = f2pack(zv[2], zv[3]);
    d2[8] = f2pack(zv[4], zv[5]);
    d2[9] = f2pack(zv[6], zv[7]);
    d2[10] = f2pack(1.f, 0.f);
    d2[11] = 0ULL;

    u64 r2[6];
    {
        const ulonglong2* bb = (const ulonglong2*)sBd2;
        #pragma unroll
        for (int q = 0; q < 3; q++) {
            ulonglong2 v = bb[q];
            r2[2*q] = v.x; r2[2*q+1] = v.y;
        }
    }

    #pragma unroll 4
    for (int h = 0; h < 32; h++) {
        const ulonglong2* w1r = (const ulonglong2*)(sWd1 + h*24);
        u64 t0 = 0ULL, t1 = 0ULL, t2 = 0ULL, t3 = 0ULL;
        #pragma unroll
        for (int q = 0; q < 6; q += 2) {
            ulonglong2 cc0 = w1r[q];
            ulonglong2 cc1 = w1r[q+1];
            t0 = f2fma(cc0.x, d2[2*q],   t0);
            t1 = f2fma(cc0.y, d2[2*q+1], t1);
            t2 = f2fma(cc1.x, d2[2*q+2], t2);
            t3 = f2fma(cc1.y, d2[2*q+3], t3);
        }
        u64 st = f2add(f2add(t0, t2), f2add(t1, t3));
        float2 u = f2unpack(st);
        float hv = fmaxf(u.x + u.y, 0.f);
        u64 hp = f2dup(hv);
        const ulonglong2* w2r = (const ulonglong2*)(sWd2 + h*12);
        #pragma unroll
        for (int q = 0; q < 3; q++) {
            ulonglong2 c = w2r[q];
            r2[2*q]   = f2fma(c.x, hp, r2[2*q]);
            r2[2*q+1] = f2fma(c.y, hp, r2[2*q+1]);
        }
    }

    float rr[12];
    #pragma unroll
    for (int q = 0; q < 6; q++) {
        float2 v = f2unpack(r2[q]);
        rr[2*q] = v.x; rr[2*q+1] = v.y;
    }
    float* out_rec = out + (size_t)b * 12;
    #pragma unroll
    for (int ii = 0; ii < 3; ii++) {
        float4 v;
        v.x = __fdividef(1.f, 1.f + __expf(-rr[ii*4+0]));
        v.y = __fdividef(1.f, 1.f + __expf(-rr[ii*4+1]));
        v.z = __fdividef(1.f, 1.f + __expf(-rr[ii*4+2]));
        v.w = __fdividef(1.f, 1.f + __expf(-rr[ii*4+3]));
        ((float4*)out_rec)[ii] = v;
    }
    float* out_mean = out + (size_t)12*BATCH + (size_t)b*8;
    ((float4*)out_mean)[0] = make_float4(mvs[0], mvs[1], mvs[2], mvs[3]);
    ((float4*)out_mean)[1] = make_float4(mvs[4], mvs[5], mvs[6], mvs[7]);
    float* out_lv = out + (size_t)20*BATCH + (size_t)b*8;
    ((float4*)out_lv)[0] = make_float4(mvs[8],  mvs[9],  mvs[10], mvs[11]);
    ((float4*)out_lv)[1] = make_float4(mvs[12], mvs[13], mvs[14], mvs[15]);
    float* out_z = out + (size_t)28*BATCH + (size_t)b*8;
    ((float4*)out_z)[0] = make_float4(zv[0], zv[1], zv[2], zv[3]);
    ((float4*)out_z)[1] = make_float4(zv[4], zv[5], zv[6], zv[7]);
}

extern "C" void kernel_launch(void* const* d_in, const int* in_sizes, int n_in,
                              void* d_out, int out_size)
{
    const float* initial_c = (const float*)d_in[0];
    // d_in[1] = initial_s (unused)
    const float* current_c = (const float*)d_in[2];
    const float* eps       = (const float*)d_in[3];
    const float* W1  = (const float*)d_in[4];
    const float* b1  = (const float*)d_in[5];
    const float* W2  = (const float*)d_in[6];
    const float* b2  = (const float*)d_in[7];
    const float* W3  = (const float*)d_in[8];
    const float* b3  = (const float*)d_in[9];
    const float* Wm  = (const float*)d_in[10];
    const float* bm  = (const float*)d_in[11];
    const float* Wv  = (const float*)d_in[12];
    const float* bv  = (const float*)d_in[13];
    const float* Wd1 = (const float*)d_in[14];
    const float* bd1 = (const float*)d_in[15];
    const float* Wd2 = (const float*)d_in[16];
    const float* bd2 = (const float*)d_in[17];
    float* out = (float*)d_out;

    cudaFuncSetAttribute(msg_kernel, cudaFuncAttributeMaxDynamicSharedMemorySize, SMEM1_BYTES);
    cudaFuncSetAttribute(dec_kernel, cudaFuncAttributeMaxDynamicSharedMemorySize, SMEM2_BYTES);

    msg_kernel<<<BATCH / NT, NT, SMEM1_BYTES>>>(current_c, W1, b1, W2, b2);
    dec_kernel<<<BATCH / NT, NT, SMEM2_BYTES>>>(initial_c, eps,
        W3, b3, Wm, bm, Wv, bv, Wd1, bd1, Wd2, bd2, out);
}

// round 15
// speedup vs baseline: 2.0148x; 1.2938x over previous
#include <cuda_runtime.h>
#include <cuda_bf16.h>
#include <math.h>

// ContextVAE, two-kernel pipeline (R15: msg GEMM moved to 3-term bf16
// mma.m16n8k16 — half the k-steps, half the mma count and B-fragment LDS;
// dec identical to R14):
//  K1 (msg): x1 @ W2^T via bf16 m16n8k16 (ahi*bhi + ahi*blo + alo*bhi).
//  K2 (dec): msum staged to smem; msum @ W3^T via 3xTF32 m16n8k8; x3 @ Wmv
//            in-fragment FFMA2 + shfl reduce; reparam + decoder scalar.

#define BATCH 262144
#define NT 256

typedef unsigned long long u64;
typedef unsigned int u32;

__device__ float g_msum[(size_t)BATCH * 40];   // 42MB scratch (row layout)

__device__ __forceinline__ u64 f2fma(u64 a, u64 b, u64 c) {
    u64 d;
    asm("fma.rn.f32x2 %0, %1, %2, %3;" : "=l"(d) : "l"(a), "l"(b), "l"(c));
    return d;
}
__device__ __forceinline__ u64 f2add(u64 a, u64 b) {
    u64 d;
    asm("add.rn.f32x2 %0, %1, %2;" : "=l"(d) : "l"(a), "l"(b));
    return d;
}
__device__ __forceinline__ u64 f2pack(float lo, float hi) {
    u64 r;
    asm("mov.b64 %0, {%1, %2};" : "=l"(r) : "f"(lo), "f"(hi));
    return r;
}
__device__ __forceinline__ u64 f2dup(float v) {
    u64 r;
    asm("mov.b64 %0, {%1, %1};" : "=l"(r) : "f"(v));
    return r;
}
__device__ __forceinline__ float2 f2unpack(u64 p) {
    float2 r;
    asm("mov.b64 {%0, %1}, %2;" : "=f"(r.x), "=f"(r.y) : "l"(p));
    return r;
}
__device__ __forceinline__ u32 f2tf32(float x) {
    u32 r;
    asm("cvt.rna.tf32.f32 %0, %1;" : "=r"(r) : "f"(x));
    return r;
}
// pack two f32 -> bf16x2; hi half = first arg, lo half = second arg.
__device__ __forceinline__ u32 pkbf(float hi, float lo) {
    u32 d;
    asm("cvt.rn.bf16x2.f32 %0, %1, %2;" : "=r"(d) : "f"(hi), "f"(lo));
    return d;
}
__device__ __forceinline__ void mma_tf32(float* d, const u32* a, const u32* b) {
    asm("mma.sync.aligned.m16n8k8.row.col.f32.tf32.tf32.f32 "
        "{%0,%1,%2,%3}, {%4,%5,%6,%7}, {%8,%9}, {%0,%1,%2,%3};"
        : "+f"(d[0]), "+f"(d[1]), "+f"(d[2]), "+f"(d[3])
        : "r"(a[0]), "r"(a[1]), "r"(a[2]), "r"(a[3]), "r"(b[0]), "r"(b[1]));
}
__device__ __forceinline__ void mma_bf16(float* d, const u32* a, const u32* b) {
    asm("mma.sync.aligned.m16n8k16.row.col.f32.bf16.bf16.f32 "
        "{%0,%1,%2,%3}, {%4,%5,%6,%7}, {%8,%9}, {%0,%1,%2,%3};"
        : "+f"(d[0]), "+f"(d[1]), "+f"(d[2]), "+f"(d[3])
        : "r"(a[0]), "r"(a[1]), "r"(a[2]), "r"(a[3]), "r"(b[0]), "r"(b[1]));
}

// ===================== K1: message stage (bf16 m16n8k16) =====================
// sW2P layout: float4 idx (ks*5+nt)*32+lane = {bhi01, bhi23, blo01, blo23}
//   n = nt*8 + (lane>>2); k pairs (K0+2c, K0+2c+1) and (K0+2c+8, K0+2c+9),
//   K0 = ks*16, c = lane&3. Each u32 = bf16x2 with low half = even k.
#define OFF1_W1W  0
#define OFF1_W1B  (OFF1_W1W + 128*4)
#define OFF1_W2P  (OFF1_W1B + 128*4)
#define OFF1_B2   (OFF1_W2P + 8*5*32*4)
#define OFF1_CUR  (OFF1_B2 + 40)
#define SMEM1_FLOATS (OFF1_CUR + 256*12)
#define SMEM1_BYTES  (SMEM1_FLOATS * 4)

__global__ __launch_bounds__(NT, 2)
void msg_kernel(const float* __restrict__ current_c,
                const float* __restrict__ W1, const float* __restrict__ b1,
                const float* __restrict__ W2, const float* __restrict__ b2)
{
    extern __shared__ float sm[];
    float* sW1w = sm + OFF1_W1W;
    float* sW1b = sm + OFF1_W1B;
    float* sW2P = sm + OFF1_W2P;
    float* sB2  = sm + OFF1_B2;
    float* sCur = sm + OFF1_CUR;

    const int t = threadIdx.x;

    for (int o = t; o < 128; o += NT) {
        sW1w[o*4+0] = __ldg(&W1[o*13 + 10]);
        sW1w[o*4+1] = __ldg(&W1[o*13 + 11]);
        sW1w[o*4+2] = __ldg(&W1[o*13 + 12]);
        sW1w[o*4+3] = 0.f;
        float bb = __ldg(&b1[o]) + __ldg(&W1[o*13 + 0]);
        #pragma unroll
        for (int e = 0; e < 4; e++)
            sW1b[o*4+e] = bb + __ldg(&W1[o*13 + 6 + e]);
    }
    // bf16-packed W2 fragments
    for (int i = t; i < 8*5*32; i += NT) {
        int ks = i / 160;
        int r  = i % 160;
        int nt = r / 32;
        int lane = r % 32;
        int rr = lane >> 2, cI = lane & 3;
        int n  = nt*8 + rr;
        int K0 = ks*16;
        float w0 = (n < 39) ? __ldg(&W2[n*128 + K0 + 2*cI])     : 0.f;
        float w1 = (n < 39) ? __ldg(&W2[n*128 + K0 + 2*cI + 1]) : 0.f;
        float w2 = (n < 39) ? __ldg(&W2[n*128 + K0 + 2*cI + 8]) : 0.f;
        float w3 = (n < 39) ? __ldg(&W2[n*128 + K0 + 2*cI + 9]) : 0.f;
        u32 hi01 = pkbf(w1, w0);
        u32 hi23 = pkbf(w3, w2);
        float f0 = __uint_as_float(hi01 << 16);
        float f1 = __uint_as_float(hi01 & 0xFFFF0000u);
        float f2 = __uint_as_float(hi23 << 16);
        float f3 = __uint_as_float(hi23 & 0xFFFF0000u);
        u32 lo01 = pkbf(w1 - f1, w0 - f0);
        u32 lo23 = pkbf(w3 - f3, w2 - f2);
        float4 pk4;
        pk4.x = __uint_as_float(hi01);
        pk4.y = __uint_as_float(hi23);
        pk4.z = __uint_as_float(lo01);
        pk4.w = __uint_as_float(lo23);
        ((float4*)sW2P)[i] = pk4;
    }
    if (t < 40) sB2[t] = (t < 39) ? __ldg(&b2[t]) : 0.f;
    {
        const int b = blockIdx.x * NT + t;
        const float* cc = current_c + (size_t)b * 30;
        #pragma unroll
        for (int e = 0; e < 4; e++) {
            sCur[t*12 + 3*e + 0] = __ldg(&cc[e]);
            sCur[t*12 + 3*e + 1] = __ldg(&cc[10 + e]);
            sCur[t*12 + 3*e + 2] = __ldg(&cc[14 + 4*e]);
        }
    }
    __syncthreads();

    const int lane = t & 31;
    const int warp = t >> 5;
    const int r0   = lane >> 2;
    const int cIdx = lane & 3;
    const int edge = r0 & 3;
    const int blockElem0 = blockIdx.x * NT;

    #pragma unroll 1
    for (int pass = 0; pass < 4; pass++) {
        const int eb = warp*32 + pass*8;

        float p[2][2][3];
        #pragma unroll
        for (int mt = 0; mt < 2; mt++)
            #pragma unroll
            for (int h = 0; h < 2; h++) {
                int e = eb + mt*4 + (r0 >> 2) + 2*h;
                p[mt][h][0] = sCur[e*12 + edge*3 + 0];
                p[mt][h][1] = sCur[e*12 + edge*3 + 1];
                p[mt][h][2] = sCur[e*12 + edge*3 + 2];
            }

        float acc[2][5][4];
        #pragma unroll
        for (int mt = 0; mt < 2; mt++)
            #pragma unroll
            for (int nt = 0; nt < 5; nt++)
                #pragma unroll
                for (int i = 0; i < 4; i++) acc[mt][nt][i] = 0.f;

        #pragma unroll 1
        for (int ks = 0; ks < 8; ks++) {
            const int ke0 = ks*16 + 2*cIdx;   // even k of pair 0
            float4 wE0 = ((const float4*)sW1w)[ke0];
            float4 wO0 = ((const float4*)sW1w)[ke0 + 1];
            float4 wE1 = ((const float4*)sW1w)[ke0 + 8];
            float4 wO1 = ((const float4*)sW1w)[ke0 + 9];
            float bE0 = sW1b[(ke0)*4 + edge];
            float bO0 = sW1b[(ke0+1)*4 + edge];
            float bE1 = sW1b[(ke0+8)*4 + edge];
            float bO1 = sW1b[(ke0+9)*4 + edge];

            u32 bhi[5][2], blo[5][2];
            #pragma unroll
            for (int nt = 0; nt < 5; nt++) {
                float4 f = ((const float4*)sW2P)[(ks*5 + nt)*32 + lane];
                bhi[nt][0] = __float_as_uint(f.x);
                bhi[nt][1] = __float_as_uint(f.y);
                blo[nt][0] = __float_as_uint(f.z);
                blo[nt][1] = __float_as_uint(f.w);
            }

            #pragma unroll
            for (int mt = 0; mt < 2; mt++) {
                // 8 x1 values: rows (h=0 -> r0, h=1 -> r0+8) x 4 k's
                float xE0[2], xO0[2], xE1[2], xO1[2];
                #pragma unroll
                for (int h = 0; h < 2; h++) {
                    const float q0 = p[mt][h][0], q1 = p[mt][h][1], q2 = p[mt][h][2];
                    xE0[h] = fmaxf(fmaf(wE0.x, q0, fmaf(wE0.y, q1, fmaf(wE0.z, q2, bE0))), 0.f);
                    xO0[h] = fmaxf(fmaf(wO0.x, q0, fmaf(wO0.y, q1, fmaf(wO0.z, q2, bO0))), 0.f);
                    xE1[h] = fmaxf(fmaf(wE1.x, q0, fmaf(wE1.y, q1, fmaf(wE1.z, q2, bE1))), 0.f);
                    xO1[h] = fmaxf(fmaf(wO1.x, q0, fmaf(wO1.y, q1, fmaf(wO1.z, q2, bO1))), 0.f);
                }
                // A fragments: a0 row r0 pair0, a1 row r0+8 pair0,
                //              a2 row r0 pair1, a3 row r0+8 pair1 (low = even k)
                u32 ahi[4], alo[4];
                ahi[0] = pkbf(xO0[0], xE0[0]);
                ahi[1] = pkbf(xO0[1], xE0[1]);
                ahi[2] = pkbf(xO1[0], xE1[0]);
                ahi[3] = pkbf(xO1[1], xE1[1]);
                {
                    float fe, fo;
                    fe = __uint_as_float(ahi[0] << 16);
                    fo = __uint_as_float(ahi[0] & 0xFFFF0000u);
                    alo[0] = pkbf(xO0[0] - fo, xE0[0] - fe);
                    fe = __uint_as_float(ahi[1] << 16);
                    fo = __uint_as_float(ahi[1] & 0xFFFF0000u);
                    alo[1] = pkbf(xO0[1] - fo, xE0[1] - fe);
                    fe = __uint_as_float(ahi[2] << 16);
                    fo = __uint_as_float(ahi[2] & 0xFFFF0000u);
                    alo[2] = pkbf(xO1[0] - fo, xE1[0] - fe);
                    fe = __uint_as_float(ahi[3] << 16);
                    fo = __uint_as_float(ahi[3] & 0xFFFF0000u);
                    alo[3] = pkbf(xO1[1] - fo, xE1[1] - fe);
                }
                #pragma unroll
                for (int nt = 0; nt < 5; nt++) {
                    mma_bf16(acc[mt][nt], ahi, bhi[nt]);
                    mma_bf16(acc[mt][nt], ahi, blo[nt]);
                    mma_bf16(acc[mt][nt], alo, bhi[nt]);
                }
            }
        }

        // epilogue: +b2, relu, edge-sum via shfl, store row layout
        #pragma unroll
        for (int mt = 0; mt < 2; mt++) {
            #pragma unroll
            for (int nt = 0; nt < 5; nt++) {
                int jb = nt*8 + cIdx*2;
                float2 b2v = *(const float2*)&sB2[jb];
                float v0 = fmaxf(acc[mt][nt][0] + b2v.x, 0.f);
                float v1 = fmaxf(acc[mt][nt][1] + b2v.y, 0.f);
                float v2 = fmaxf(acc[mt][nt][2] + b2v.x, 0.f);
                float v3 = fmaxf(acc[mt][nt][3] + b2v.y, 0.f);
                v0 += __shfl_xor_sync(0xffffffffu, v0, 4);
                v1 += __shfl_xor_sync(0xffffffffu, v1, 4);
                v2 += __shfl_xor_sync(0xffffffffu, v2, 4);
                v3 += __shfl_xor_sync(0xffffffffu, v3, 4);
                v0 += __shfl_xor_sync(0xffffffffu, v0, 8);
                v1 += __shfl_xor_sync(0xffffffffu, v1, 8);
                v2 += __shfl_xor_sync(0xffffffffu, v2, 8);
                v3 += __shfl_xor_sync(0xffffffffu, v3, 8);
                if (edge == 0) {
                    int eLo = blockElem0 + eb + mt*4 + (r0 >> 2);
                    *(float2*)&g_msum[(size_t)eLo*40 + jb]     = make_float2(v0, v1);
                    *(float2*)&g_msum[(size_t)(eLo+2)*40 + jb] = make_float2(v2, v3);
                }
            }
        }
    }
}

// ===================== K2: readout on tensor cores + decoder (= R14) ==========
#define OFF2_W3P  0
#define OFF2_WMVP (OFF2_W3P + 16*5*32*4)      // 10240
#define OFF2_WD1  (OFF2_WMVP + 16*4*9*4)      // 12544
#define OFF2_WD2  (OFF2_WD1 + 32*24)          // 13312
#define OFF2_BMV  (OFF2_WD2 + 32*12)          // 13696
#define OFF2_BD2  (OFF2_BMV + 16)             // 13712
#define OFF2_MV   (OFF2_BD2 + 16)             // 13728, 16B aligned
#define OFF2_MS   (OFF2_MV + 256*20)          // warp-private msum stage
#define MS_STRIDE 44
#define SMEM2_FLOATS (OFF2_MS + 8*16*MS_STRIDE)
#define SMEM2_BYTES  (SMEM2_FLOATS * 4)

__global__ __launch_bounds__(NT, 2)
void dec_kernel(const float* __restrict__ initial_c,
                const float* __restrict__ eps,
                const float* __restrict__ W3, const float* __restrict__ b3,
                const float* __restrict__ Wm, const float* __restrict__ bm,
                const float* __restrict__ Wv, const float* __restrict__ bv,
                const float* __restrict__ Wd1, const float* __restrict__ bd1,
                const float* __restrict__ Wd2, const float* __restrict__ bd2,
                float* __restrict__ out)
{
    extern __shared__ float sm[];
    float* sW3P  = sm + OFF2_W3P;
    float* sWmvP = sm + OFF2_WMVP;
    float* sWd1  = sm + OFF2_WD1;
    float* sWd2  = sm + OFF2_WD2;
    float* sBmv  = sm + OFF2_BMV;
    float* sBd2  = sm + OFF2_BD2;
    float* sMV   = sm + OFF2_MV;

    const int t = threadIdx.x;

    for (int i = t; i < 16*5*32; i += NT) {
        int ntG = i / 160;
        int r   = i % 160;
        int ks  = r / 32;
        int ln  = r % 32;
        int rr0 = ln >> 2, cI = ln & 3;
        int n  = ntG*8 + rr0;
        int k0 = ks*8 + cI;
        int k4 = k0 + 4;
        float w0 = __ldg(&W3[n*39 + k0]);
        float w4 = (k4 < 39) ? __ldg(&W3[n*39 + k4]) : __ldg(&b3[n]);
        float h0 = __uint_as_float(f2tf32(w0));
        float h4 = __uint_as_float(f2tf32(w4));
        float l0 = __uint_as_float(f2tf32(w0 - h0));
        float l4 = __uint_as_float(f2tf32(w4 - h4));
        ((float4*)sW3P)[i] = make_float4(h0, h4, l0, l4);
    }
    for (int i = t; i < 16*4*8; i += NT) {
        int ht = i / 32;
        int rr = i % 32;
        int cI = rr / 8;
        int q  = rr % 8;
        int j  = ht*8 + 2*cI + (q >> 2);
        int ch = q & 3;
        float v[4];
        #pragma unroll
        for (int c = 0; c < 4; c++) {
            int q16 = ch*4 + c;
            v[c] = (q16 < 8) ? __ldg(&Wm[q16*128 + j]) : __ldg(&Wv[(q16-8)*128 + j]);
        }
        ((float4*)(sWmvP + ((ht*4 + cI)*9 + q)*4))[0] = make_float4(v[0], v[1], v[2], v[3]);
    }
    for (int i = t; i < 32*24; i += NT) {
        int h = i / 24, q = i % 24;
        float v;
        if (q < 12)       v = __ldg(&Wd1[h*25 + 5 + q]);
        else if (q < 20)  v = __ldg(&Wd1[h*25 + 17 + (q-12)]);
        else if (q == 20) v = __ldg(&bd1[h]) + __ldg(&Wd1[h*25 + 0]);
        else              v = 0.f;
        sWd1[i] = v;
    }
    for (int i = t; i < 32*12; i += NT) {
        int h = i / 12, j = i % 12;
        sWd2[i] = __ldg(&Wd2[j*32 + h]);
    }
    if (t < 16) sBmv[t] = (t < 8) ? __ldg(&bm[t]) : __ldg(&bv[t-8]);
    if (t < 12) sBd2[t] = __ldg(&bd2[t]);
    __syncthreads();

    const int lane = t & 31;
    const int warp = t >> 5;
    const int r0   = lane >> 2;
    const int cIdx = lane & 3;
    const int warpE0 = blockIdx.x * NT + warp*32;
    const int locE0  = warp*32;
    float* sMSw = sm + OFF2_MS + warp * 16 * MS_STRIDE;

    #pragma unroll 1
    for (int pass = 0; pass < 2; pass++) {
        __syncwarp();
        {
            const float4* src = (const float4*)(g_msum + (size_t)(warpE0 + pass*16) * 40);
            #pragma unroll
            for (int it = 0; it < 5; it++) {
                int idx = it*32 + lane;
                float4 v = __ldg(&src[idx]);
                int e = idx / 10, c = idx % 10;
                *(float4*)&sMSw[e*MS_STRIDE + c*4] = v;
            }
        }
        __syncwarp();

        float msR0[10], msR8[10];
        #pragma unroll
        for (int i = 0; i < 10; i++) {
            msR0[i] = sMSw[r0*MS_STRIDE + cIdx + 4*i];
            msR8[i] = sMSw[(r0+8)*MS_STRIDE + cIdx + 4*i];
        }
        if (cIdx == 3) { msR0[9] = 1.0f; msR8[9] = 1.0f; }

        u64 pA[8], pB[8];
        #pragma unroll
        for (int q = 0; q < 8; q++) { pA[q] = 0ULL; pB[q] = 0ULL; }

        #pragma unroll 1
        for (int half = 0; half < 2; half++) {
            float acc[8][4];
            #pragma unroll
            for (int nt = 0; nt < 8; nt++)
                #pragma unroll
                for (int i = 0; i < 4; i++) acc[nt][i] = 0.f;

            #pragma unroll
            for (int ks = 0; ks < 5; ks++) {
                u32 ahi[4], alo[4];
                {
                    float a0 = msR0[2*ks], a1 = msR8[2*ks];
                    float a2 = msR0[2*ks+1], a3 = msR8[2*ks+1];
                    ahi[0] = f2tf32(a0); ahi[1] = f2tf32(a1);
                    ahi[2] = f2tf32(a2); ahi[3] = f2tf32(a3);
                    alo[0] = f2tf32(a0 - __uint_as_float(ahi[0]));
                    alo[1] = f2tf32(a1 - __uint_as_float(ahi[1]));
                    alo[2] = f2tf32(a2 - __uint_as_float(ahi[2]));
                    alo[3] = f2tf32(a3 - __uint_as_float(ahi[3]));
                }
                #pragma unroll
                for (int nt = 0; nt < 8; nt++) {
                    float4 f = ((const float4*)sW3P)[((half*8 + nt)*5 + ks)*32 + lane];
                    u32 bhi[2] = {__float_as_uint(f.x), __float_as_uint(f.y)};
                    u32 blo[2] = {__float_as_uint(f.z), __float_as_uint(f.w)};
                    mma_tf32(acc[nt], ahi, bhi);
                    mma_tf32(acc[nt], ahi, blo);
                    mma_tf32(acc[nt], alo, bhi);
                }
            }

            #pragma unroll
            for (int nt = 0; nt < 8; nt++) {
                int ht = half*8 + nt;
                const ulonglong2* wp = (const ulonglong2*)(sWmvP + ((ht*4 + cIdx)*9)*4);
                float xA0 = fmaxf(acc[nt][0], 0.f);
                float xA1 = fmaxf(acc[nt][1], 0.f);
                float xB0 = fmaxf(acc[nt][2], 0.f);
                float xB1 = fmaxf(acc[nt][3], 0.f);
                u64 dA0 = f2dup(xA0), dA1 = f2dup(xA1);
                u64 dB0 = f2dup(xB0), dB1 = f2dup(xB1);
                #pragma unroll
                for (int q = 0; q < 4; q++) {
                    ulonglong2 c0v = wp[q];
                    ulonglong2 c1v = wp[4 + q];
                    pA[2*q]   = f2fma(c0v.x, dA0, pA[2*q]);
                    pA[2*q+1] = f2fma(c0v.y, dA0, pA[2*q+1]);
                    pA[2*q]   = f2fma(c1v.x, dA1, pA[2*q]);
                    pA[2*q+1] = f2fma(c1v.y, dA1, pA[2*q+1]);
                    pB[2*q]   = f2fma(c0v.x, dB0, pB[2*q]);
                    pB[2*q+1] = f2fma(c0v.y, dB0, pB[2*q+1]);
                    pB[2*q]   = f2fma(c1v.x, dB1, pB[2*q]);
                    pB[2*q+1] = f2fma(c1v.y, dB1, pB[2*q+1]);
                }
            }
        }

        #pragma unroll
        for (int q = 0; q < 8; q++) {
            pA[q] = f2add(pA[q], __shfl_xor_sync(0xffffffffu, pA[q], 1));
            pB[q] = f2add(pB[q], __shfl_xor_sync(0xffffffffu, pB[q], 1));
            pA[q] = f2add(pA[q], __shfl_xor_sync(0xffffffffu, pA[q], 2));
            pB[q] = f2add(pB[q], __shfl_xor_sync(0xffffffffu, pB[q], 2));
        }
        {
            int eA = locE0 + pass*16 + r0;
            int eB = eA + 8;
            float4 bq = *(const float4*)&sBmv[4*cIdx];
            float2 a0 = f2unpack(pA[2*cIdx]);
            float2 a1 = f2unpack(pA[2*cIdx+1]);
            float2 b0 = f2unpack(pB[2*cIdx]);
            float2 b1 = f2unpack(pB[2*cIdx+1]);
            *(float4*)&sMV[eA*20 + 4*cIdx] =
                make_float4(a0.x + bq.x, a0.y + bq.y, a1.x + bq.z, a1.y + bq.w);
            *(float4*)&sMV[eB*20 + 4*cIdx] =
                make_float4(b0.x + bq.x, b0.y + bq.y, b1.x + bq.z, b1.y + bq.w);
        }
    }
    __syncwarp();

    // ======== reparam + decoder: 1 element/thread ========
    const int b = blockIdx.x * NT + t;
    float mvs[16];
    {
        const float4* mvp = (const float4*)&sMV[t*20];
        #pragma unroll
        for (int q = 0; q < 4; q++) {
            float4 v = mvp[q];
            mvs[4*q+0] = v.x; mvs[4*q+1] = v.y; mvs[4*q+2] = v.z; mvs[4*q+3] = v.w;
        }
    }

    const float4* epv = (const float4*)(eps + (size_t)b * 8);
    float4 e0 = epv[0], e1 = epv[1];
    float ev[8] = {e0.x, e0.y, e0.z, e0.w, e1.x, e1.y, e1.z, e1.w};
    float zv[8];
    #pragma unroll
    for (int i = 0; i < 8; i++)
        zv[i] = fmaf(ev[i], __expf(0.5f * mvs[8+i]), mvs[i]);

    const float* ic = initial_c + (size_t)b * 30;
    u64 d2[12];
    d2[0] = f2pack(__ldg(&ic[0]),  __ldg(&ic[1]));
    d2[1] = f2pack(__ldg(&ic[2]),  __ldg(&ic[3]));
    d2[2] = f2pack(__ldg(&ic[10]), __ldg(&ic[11]));
    d2[3] = f2pack(__ldg(&ic[12]), __ldg(&ic[13]));
    d2[4] = f2pack(__ldg(&ic[14]), __ldg(&ic[18]));
    d2[5] = f2pack(__ldg(&ic[22]), __ldg(&ic[26]));
    d2[6] = f2pack(zv[0], zv[1]);
    d2[7] = f2pack(zv[2], zv[3]);
    d2[8] = f2pack(zv[4], zv[5]);
    d2[9] = f2pack(zv[6], zv[7]);
    d2[10] = f2pack(1.f, 0.f);
    d2[11] = 0ULL;

    u64 r2[6];
    {
        const ulonglong2* bb = (const ulonglong2*)sBd2;
        #pragma unroll
        for (int q = 0; q < 3; q++) {
            ulonglong2 v = bb[q];
            r2[2*q] = v.x; r2[2*q+1] = v.y;
        }
    }

    #pragma unroll 4
    for (int h = 0; h < 32; h++) {
        const ulonglong2* w1r = (const ulonglong2*)(sWd1 + h*24);
        u64 t0 = 0ULL, t1 = 0ULL, t2 = 0ULL, t3 = 0ULL;
        #pragma unroll
        for (int q = 0; q < 6; q += 2) {
            ulonglong2 cc0 = w1r[q];
            ulonglong2 cc1 = w1r[q+1];
            t0 = f2fma(cc0.x, d2[2*q],   t0);
            t1 = f2fma(cc0.y, d2[2*q+1], t1);
            t2 = f2fma(cc1.x, d2[2*q+2], t2);
            t3 = f2fma(cc1.y, d2[2*q+3], t3);
        }
        u64 st = f2add(f2add(t0, t2), f2add(t1, t3));
        float2 u = f2unpack(st);
        float hv = fmaxf(u.x + u.y, 0.f);
        u64 hp = f2dup(hv);
        const ulonglong2* w2r = (const ulonglong2*)(sWd2 + h*12);
        #pragma unroll
        for (int q = 0; q < 3; q++) {
            ulonglong2 c = w2r[q];
            r2[2*q]   = f2fma(c.x, hp, r2[2*q]);
            r2[2*q+1] = f2fma(c.y, hp, r2[2*q+1]);
        }
    }

    float rr[12];
    #pragma unroll
    for (int q = 0; q < 6; q++) {
        float2 v = f2unpack(r2[q]);
        rr[2*q] = v.x; rr[2*q+1] = v.y;
    }
    float* out_rec = out + (size_t)b * 12;
    #pragma unroll
    for (int ii = 0; ii < 3; ii++) {
        float4 v;
        v.x = __fdividef(1.f, 1.f + __expf(-rr[ii*4+0]));
        v.y = __fdividef(1.f, 1.f + __expf(-rr[ii*4+1]));
        v.z = __fdividef(1.f, 1.f + __expf(-rr[ii*4+2]));
        v.w = __fdividef(1.f, 1.f + __expf(-rr[ii*4+3]));
        ((float4*)out_rec)[ii] = v;
    }
    float* out_mean = out + (size_t)12*BATCH + (size_t)b*8;
    ((float4*)out_mean)[0] = make_float4(mvs[0], mvs[1], mvs[2], mvs[3]);
    ((float4*)out_mean)[1] = make_float4(mvs[4], mvs[5], mvs[6], mvs[7]);
    float* out_lv = out + (size_t)20*BATCH + (size_t)b*8;
    ((float4*)out_lv)[0] = make_float4(mvs[8],  mvs[9],  mvs[10], mvs[11]);
    ((float4*)out_lv)[1] = make_float4(mvs[12], mvs[13], mvs[14], mvs[15]);
    float* out_z = out + (size_t)28*BATCH + (size_t)b*8;
    ((float4*)out_z)[0] = make_float4(zv[0], zv[1], zv[2], zv[3]);
    ((float4*)out_z)[1] = make_float4(zv[4], zv[5], zv[6], zv[7]);
}

extern "C" void kernel_launch(void* const* d_in, const int* in_sizes, int n_in,
                              void* d_out, int out_size)
{
    const float* initial_c = (const float*)d_in[0];
    // d_in[1] = initial_s (unused)
    const float* current_c = (const float*)d_in[2];
    const float* eps       = (const float*)d_in[3];
    const float* W1  = (const float*)d_in[4];
    const float* b1  = (const float*)d_in[5];
    const float* W2  = (const float*)d_in[6];
    const float* b2  = (const float*)d_in[7];
    const float* W3  = (const float*)d_in[8];
    const float* b3  = (const float*)d_in[9];
    const float* Wm  = (const float*)d_in[10];
    const float* bm  = (const float*)d_in[11];
    const float* Wv  = (const float*)d_in[12];
    const float* bv  = (const float*)d_in[13];
    const float* Wd1 = (const float*)d_in[14];
    const float* bd1 = (const float*)d_in[15];
    const float* Wd2 = (const float*)d_in[16];
    const float* bd2 = (const float*)d_in[17];
    float* out = (float*)d_out;

    cudaFuncSetAttribute(msg_kernel, cudaFuncAttributeMaxDynamicSharedMemorySize, SMEM1_BYTES);
    cudaFuncSetAttribute(dec_kernel, cudaFuncAttributeMaxDynamicSharedMemorySize, SMEM2_BYTES);

    msg_kernel<<<BATCH / NT, NT, SMEM1_BYTES>>>(current_c, W1, b1, W2, b2);
    dec_kernel<<<BATCH / NT, NT, SMEM2_BYTES>>>(initial_c, eps,
        W3, b3, Wm, bm, Wv, bv, Wd1, bd1, Wd2, bd2, out);
}

// round 16
// speedup vs baseline: 2.1667x; 1.0754x over previous
#include <cuda_runtime.h>
#include <cuda_bf16.h>
#include <math.h>

// ContextVAE, two-kernel pipeline (R16: dec's W3 GEMM also moved to 3-term
// bf16 mma.m16n8k16 with K padded 40->48; msg identical to R15):
//  K1 (msg): x1 @ W2^T via bf16 m16n8k16 (ahi*bhi + ahi*blo + alo*bhi).
//  K2 (dec): msum staged to smem; msum @ W3^T via bf16 m16n8k16 (3 k-steps);
//            x3 @ Wmv in-fragment FFMA2 + shfl reduce; reparam + decoder.

#define BATCH 262144
#define NT 256

typedef unsigned long long u64;
typedef unsigned int u32;

__device__ float g_msum[(size_t)BATCH * 40];   // 42MB scratch (row layout)

__device__ __forceinline__ u64 f2fma(u64 a, u64 b, u64 c) {
    u64 d;
    asm("fma.rn.f32x2 %0, %1, %2, %3;" : "=l"(d) : "l"(a), "l"(b), "l"(c));
    return d;
}
__device__ __forceinline__ u64 f2add(u64 a, u64 b) {
    u64 d;
    asm("add.rn.f32x2 %0, %1, %2;" : "=l"(d) : "l"(a), "l"(b));
    return d;
}
__device__ __forceinline__ u64 f2pack(float lo, float hi) {
    u64 r;
    asm("mov.b64 %0, {%1, %2};" : "=l"(r) : "f"(lo), "f"(hi));
    return r;
}
__device__ __forceinline__ u64 f2dup(float v) {
    u64 r;
    asm("mov.b64 %0, {%1, %1};" : "=l"(r) : "f"(v));
    return r;
}
__device__ __forceinline__ float2 f2unpack(u64 p) {
    float2 r;
    asm("mov.b64 {%0, %1}, %2;" : "=f"(r.x), "=f"(r.y) : "l"(p));
    return r;
}
// pack two f32 -> bf16x2; hi half = first arg, lo half = second arg.
__device__ __forceinline__ u32 pkbf(float hi, float lo) {
    u32 d;
    asm("cvt.rn.bf16x2.f32 %0, %1, %2;" : "=r"(d) : "f"(hi), "f"(lo));
    return d;
}
__device__ __forceinline__ void mma_bf16(float* d, const u32* a, const u32* b) {
    asm("mma.sync.aligned.m16n8k16.row.col.f32.bf16.bf16.f32 "
        "{%0,%1,%2,%3}, {%4,%5,%6,%7}, {%8,%9}, {%0,%1,%2,%3};"
        : "+f"(d[0]), "+f"(d[1]), "+f"(d[2]), "+f"(d[3])
        : "r"(a[0]), "r"(a[1]), "r"(a[2]), "r"(a[3]), "r"(b[0]), "r"(b[1]));
}

// ===================== K1: message stage (bf16 m16n8k16, = R15) ===============
#define OFF1_W1W  0
#define OFF1_W1B  (OFF1_W1W + 128*4)
#define OFF1_W2P  (OFF1_W1B + 128*4)
#define OFF1_B2   (OFF1_W2P + 8*5*32*4)
#define OFF1_CUR  (OFF1_B2 + 40)
#define SMEM1_FLOATS (OFF1_CUR + 256*12)
#define SMEM1_BYTES  (SMEM1_FLOATS * 4)

__global__ __launch_bounds__(NT, 2)
void msg_kernel(const float* __restrict__ current_c,
                const float* __restrict__ W1, const float* __restrict__ b1,
                const float* __restrict__ W2, const float* __restrict__ b2)
{
    extern __shared__ float sm[];
    float* sW1w = sm + OFF1_W1W;
    float* sW1b = sm + OFF1_W1B;
    float* sW2P = sm + OFF1_W2P;
    float* sB2  = sm + OFF1_B2;
    float* sCur = sm + OFF1_CUR;

    const int t = threadIdx.x;

    for (int o = t; o < 128; o += NT) {
        sW1w[o*4+0] = __ldg(&W1[o*13 + 10]);
        sW1w[o*4+1] = __ldg(&W1[o*13 + 11]);
        sW1w[o*4+2] = __ldg(&W1[o*13 + 12]);
        sW1w[o*4+3] = 0.f;
        float bb = __ldg(&b1[o]) + __ldg(&W1[o*13 + 0]);
        #pragma unroll
        for (int e = 0; e < 4; e++)
            sW1b[o*4+e] = bb + __ldg(&W1[o*13 + 6 + e]);
    }
    for (int i = t; i < 8*5*32; i += NT) {
        int ks = i / 160;
        int r  = i % 160;
        int nt = r / 32;
        int lane = r % 32;
        int rr = lane >> 2, cI = lane & 3;
        int n  = nt*8 + rr;
        int K0 = ks*16;
        float w0 = (n < 39) ? __ldg(&W2[n*128 + K0 + 2*cI])     : 0.f;
        float w1 = (n < 39) ? __ldg(&W2[n*128 + K0 + 2*cI + 1]) : 0.f;
        float w2 = (n < 39) ? __ldg(&W2[n*128 + K0 + 2*cI + 8]) : 0.f;
        float w3 = (n < 39) ? __ldg(&W2[n*128 + K0 + 2*cI + 9]) : 0.f;
        u32 hi01 = pkbf(w1, w0);
        u32 hi23 = pkbf(w3, w2);
        float f0 = __uint_as_float(hi01 << 16);
        float f1 = __uint_as_float(hi01 & 0xFFFF0000u);
        float f2 = __uint_as_float(hi23 << 16);
        float f3 = __uint_as_float(hi23 & 0xFFFF0000u);
        u32 lo01 = pkbf(w1 - f1, w0 - f0);
        u32 lo23 = pkbf(w3 - f3, w2 - f2);
        float4 pk4;
        pk4.x = __uint_as_float(hi01);
        pk4.y = __uint_as_float(hi23);
        pk4.z = __uint_as_float(lo01);
        pk4.w = __uint_as_float(lo23);
        ((float4*)sW2P)[i] = pk4;
    }
    if (t < 40) sB2[t] = (t < 39) ? __ldg(&b2[t]) : 0.f;
    {
        const int b = blockIdx.x * NT + t;
        const float* cc = current_c + (size_t)b * 30;
        #pragma unroll
        for (int e = 0; e < 4; e++) {
            sCur[t*12 + 3*e + 0] = __ldg(&cc[e]);
            sCur[t*12 + 3*e + 1] = __ldg(&cc[10 + e]);
            sCur[t*12 + 3*e + 2] = __ldg(&cc[14 + 4*e]);
        }
    }
    __syncthreads();

    const int lane = t & 31;
    const int warp = t >> 5;
    const int r0   = lane >> 2;
    const int cIdx = lane & 3;
    const int edge = r0 & 3;
    const int blockElem0 = blockIdx.x * NT;

    #pragma unroll 1
    for (int pass = 0; pass < 4; pass++) {
        const int eb = warp*32 + pass*8;

        float p[2][2][3];
        #pragma unroll
        for (int mt = 0; mt < 2; mt++)
            #pragma unroll
            for (int h = 0; h < 2; h++) {
                int e = eb + mt*4 + (r0 >> 2) + 2*h;
                p[mt][h][0] = sCur[e*12 + edge*3 + 0];
                p[mt][h][1] = sCur[e*12 + edge*3 + 1];
                p[mt][h][2] = sCur[e*12 + edge*3 + 2];
            }

        float acc[2][5][4];
        #pragma unroll
        for (int mt = 0; mt < 2; mt++)
            #pragma unroll
            for (int nt = 0; nt < 5; nt++)
                #pragma unroll
                for (int i = 0; i < 4; i++) acc[mt][nt][i] = 0.f;

        #pragma unroll 1
        for (int ks = 0; ks < 8; ks++) {
            const int ke0 = ks*16 + 2*cIdx;
            float4 wE0 = ((const float4*)sW1w)[ke0];
            float4 wO0 = ((const float4*)sW1w)[ke0 + 1];
            float4 wE1 = ((const float4*)sW1w)[ke0 + 8];
            float4 wO1 = ((const float4*)sW1w)[ke0 + 9];
            float bE0 = sW1b[(ke0)*4 + edge];
            float bO0 = sW1b[(ke0+1)*4 + edge];
            float bE1 = sW1b[(ke0+8)*4 + edge];
            float bO1 = sW1b[(ke0+9)*4 + edge];

            u32 bhi[5][2], blo[5][2];
            #pragma unroll
            for (int nt = 0; nt < 5; nt++) {
                float4 f = ((const float4*)sW2P)[(ks*5 + nt)*32 + lane];
                bhi[nt][0] = __float_as_uint(f.x);
                bhi[nt][1] = __float_as_uint(f.y);
                blo[nt][0] = __float_as_uint(f.z);
                blo[nt][1] = __float_as_uint(f.w);
            }

            #pragma unroll
            for (int mt = 0; mt < 2; mt++) {
                float xE0[2], xO0[2], xE1[2], xO1[2];
                #pragma unroll
                for (int h = 0; h < 2; h++) {
                    const float q0 = p[mt][h][0], q1 = p[mt][h][1], q2 = p[mt][h][2];
                    xE0[h] = fmaxf(fmaf(wE0.x, q0, fmaf(wE0.y, q1, fmaf(wE0.z, q2, bE0))), 0.f);
                    xO0[h] = fmaxf(fmaf(wO0.x, q0, fmaf(wO0.y, q1, fmaf(wO0.z, q2, bO0))), 0.f);
                    xE1[h] = fmaxf(fmaf(wE1.x, q0, fmaf(wE1.y, q1, fmaf(wE1.z, q2, bE1))), 0.f);
                    xO1[h] = fmaxf(fmaf(wO1.x, q0, fmaf(wO1.y, q1, fmaf(wO1.z, q2, bO1))), 0.f);
                }
                u32 ahi[4], alo[4];
                ahi[0] = pkbf(xO0[0], xE0[0]);
                ahi[1] = pkbf(xO0[1], xE0[1]);
                ahi[2] = pkbf(xO1[0], xE1[0]);
                ahi[3] = pkbf(xO1[1], xE1[1]);
                {
                    float fe, fo;
                    fe = __uint_as_float(ahi[0] << 16);
                    fo = __uint_as_float(ahi[0] & 0xFFFF0000u);
                    alo[0] = pkbf(xO0[0] - fo, xE0[0] - fe);
                    fe = __uint_as_float(ahi[1] << 16);
                    fo = __uint_as_float(ahi[1] & 0xFFFF0000u);
                    alo[1] = pkbf(xO0[1] - fo, xE0[1] - fe);
                    fe = __uint_as_float(ahi[2] << 16);
                    fo = __uint_as_float(ahi[2] & 0xFFFF0000u);
                    alo[2] = pkbf(xO1[0] - fo, xE1[0] - fe);
                    fe = __uint_as_float(ahi[3] << 16);
                    fo = __uint_as_float(ahi[3] & 0xFFFF0000u);
                    alo[3] = pkbf(xO1[1] - fo, xE1[1] - fe);
                }
                #pragma unroll
                for (int nt = 0; nt < 5; nt++) {
                    mma_bf16(acc[mt][nt], ahi, bhi[nt]);
                    mma_bf16(acc[mt][nt], ahi, blo[nt]);
                    mma_bf16(acc[mt][nt], alo, bhi[nt]);
                }
            }
        }

        #pragma unroll
        for (int mt = 0; mt < 2; mt++) {
            #pragma unroll
            for (int nt = 0; nt < 5; nt++) {
                int jb = nt*8 + cIdx*2;
                float2 b2v = *(const float2*)&sB2[jb];
                float v0 = fmaxf(acc[mt][nt][0] + b2v.x, 0.f);
                float v1 = fmaxf(acc[mt][nt][1] + b2v.y, 0.f);
                float v2 = fmaxf(acc[mt][nt][2] + b2v.x, 0.f);
                float v3 = fmaxf(acc[mt][nt][3] + b2v.y, 0.f);
                v0 += __shfl_xor_sync(0xffffffffu, v0, 4);
                v1 += __shfl_xor_sync(0xffffffffu, v1, 4);
                v2 += __shfl_xor_sync(0xffffffffu, v2, 4);
                v3 += __shfl_xor_sync(0xffffffffu, v3, 4);
                v0 += __shfl_xor_sync(0xffffffffu, v0, 8);
                v1 += __shfl_xor_sync(0xffffffffu, v1, 8);
                v2 += __shfl_xor_sync(0xffffffffu, v2, 8);
                v3 += __shfl_xor_sync(0xffffffffu, v3, 8);
                if (edge == 0) {
                    int eLo = blockElem0 + eb + mt*4 + (r0 >> 2);
                    *(float2*)&g_msum[(size_t)eLo*40 + jb]     = make_float2(v0, v1);
                    *(float2*)&g_msum[(size_t)(eLo+2)*40 + jb] = make_float2(v2, v3);
                }
            }
        }
    }
}

// ===================== K2: readout (bf16 k16) + decoder =======================
// sW3P: float4 idx (ntG*3+ks)*32+lane = {bhi01, bhi23, blo01, blo23}
//   n = ntG*8 + (lane>>2); K0 = ks*16; k pairs (K0+2c, K0+2c+1), (K0+2c+8, +9);
//   val(k) = W3[n][k] for k<39, b3[n] at k=39, 0 for k>=40.
#define OFF2_W3P  0
#define OFF2_WMVP (OFF2_W3P + 16*3*32*4)      // 6144
#define OFF2_WD1  (OFF2_WMVP + 16*4*9*4)      // 8448
#define OFF2_WD2  (OFF2_WD1 + 32*24)          // 9216
#define OFF2_BMV  (OFF2_WD2 + 32*12)          // 9600
#define OFF2_BD2  (OFF2_BMV + 16)             // 9616
#define OFF2_MV   (OFF2_BD2 + 16)             // 9632, 16B aligned
#define OFF2_MS   (OFF2_MV + 256*20)          // warp-private msum stage
#define MS_STRIDE 44
#define SMEM2_FLOATS (OFF2_MS + 8*16*MS_STRIDE)
#define SMEM2_BYTES  (SMEM2_FLOATS * 4)

__global__ __launch_bounds__(NT, 2)
void dec_kernel(const float* __restrict__ initial_c,
                const float* __restrict__ eps,
                const float* __restrict__ W3, const float* __restrict__ b3,
                const float* __restrict__ Wm, const float* __restrict__ bm,
                const float* __restrict__ Wv, const float* __restrict__ bv,
                const float* __restrict__ Wd1, const float* __restrict__ bd1,
                const float* __restrict__ Wd2, const float* __restrict__ bd2,
                float* __restrict__ out)
{
    extern __shared__ float sm[];
    float* sW3P  = sm + OFF2_W3P;
    float* sWmvP = sm + OFF2_WMVP;
    float* sWd1  = sm + OFF2_WD1;
    float* sWd2  = sm + OFF2_WD2;
    float* sBmv  = sm + OFF2_BMV;
    float* sBd2  = sm + OFF2_BD2;
    float* sMV   = sm + OFF2_MV;

    const int t = threadIdx.x;

    // bf16 fragment-packed W3 (+ b3 at k=39, 0 beyond)
    for (int i = t; i < 16*3*32; i += NT) {
        int ntG = i / 96;
        int r   = i % 96;
        int ks  = r / 32;
        int ln  = r % 32;
        int rr0 = ln >> 2, cI = ln & 3;
        int n  = ntG*8 + rr0;
        int K0 = ks*16;
        int ka = K0 + 2*cI, kb = ka + 1, kc = ka + 8, kd = kc + 1;
        float w0 = (ka < 39) ? __ldg(&W3[n*39 + ka]) : ((ka == 39) ? __ldg(&b3[n]) : 0.f);
        float w1 = (kb < 39) ? __ldg(&W3[n*39 + kb]) : ((kb == 39) ? __ldg(&b3[n]) : 0.f);
        float w2 = (kc < 39) ? __ldg(&W3[n*39 + kc]) : ((kc == 39) ? __ldg(&b3[n]) : 0.f);
        float w3v = (kd < 39) ? __ldg(&W3[n*39 + kd]) : ((kd == 39) ? __ldg(&b3[n]) : 0.f);
        u32 hi01 = pkbf(w1, w0);
        u32 hi23 = pkbf(w3v, w2);
        float f0 = __uint_as_float(hi01 << 16);
        float f1 = __uint_as_float(hi01 & 0xFFFF0000u);
        float f2 = __uint_as_float(hi23 << 16);
        float f3 = __uint_as_float(hi23 & 0xFFFF0000u);
        u32 lo01 = pkbf(w1 - f1, w0 - f0);
        u32 lo23 = pkbf(w3v - f3, w2 - f2);
        float4 pk4;
        pk4.x = __uint_as_float(hi01);
        pk4.y = __uint_as_float(hi23);
        pk4.z = __uint_as_float(lo01);
        pk4.w = __uint_as_float(lo23);
        ((float4*)sW3P)[i] = pk4;
    }
    for (int i = t; i < 16*4*8; i += NT) {
        int ht = i / 32;
        int rr = i % 32;
        int cI = rr / 8;
        int q  = rr % 8;
        int j  = ht*8 + 2*cI + (q >> 2);
        int ch = q & 3;
        float v[4];
        #pragma unroll
        for (int c = 0; c < 4; c++) {
            int q16 = ch*4 + c;
            v[c] = (q16 < 8) ? __ldg(&Wm[q16*128 + j]) : __ldg(&Wv[(q16-8)*128 + j]);
        }
        ((float4*)(sWmvP + ((ht*4 + cI)*9 + q)*4))[0] = make_float4(v[0], v[1], v[2], v[3]);
    }
    for (int i = t; i < 32*24; i += NT) {
        int h = i / 24, q = i % 24;
        float v;
        if (q < 12)       v = __ldg(&Wd1[h*25 + 5 + q]);
        else if (q < 20)  v = __ldg(&Wd1[h*25 + 17 + (q-12)]);
        else if (q == 20) v = __ldg(&bd1[h]) + __ldg(&Wd1[h*25 + 0]);
        else              v = 0.f;
        sWd1[i] = v;
    }
    for (int i = t; i < 32*12; i += NT) {
        int h = i / 12, j = i % 12;
        sWd2[i] = __ldg(&Wd2[j*32 + h]);
    }
    if (t < 16) sBmv[t] = (t < 8) ? __ldg(&bm[t]) : __ldg(&bv[t-8]);
    if (t < 12) sBd2[t] = __ldg(&bd2[t]);
    __syncthreads();

    const int lane = t & 31;
    const int warp = t >> 5;
    const int r0   = lane >> 2;
    const int cIdx = lane & 3;
    const int warpE0 = blockIdx.x * NT + warp*32;
    const int locE0  = warp*32;
    float* sMSw = sm + OFF2_MS + warp * 16 * MS_STRIDE;

    #pragma unroll 1
    for (int pass = 0; pass < 2; pass++) {
        __syncwarp();
        {
            const float4* src = (const float4*)(g_msum + (size_t)(warpE0 + pass*16) * 40);
            #pragma unroll
            for (int it = 0; it < 5; it++) {
                int idx = it*32 + lane;
                float4 v = __ldg(&src[idx]);
                int e = idx / 10, c = idx % 10;
                *(float4*)&sMSw[e*MS_STRIDE + c*4] = v;
            }
        }
        __syncwarp();

        // A fragments (bf16 k16), half-independent -> computed once per pass
        u32 ahi[3][4], alo[3][4];
        #pragma unroll
        for (int ks = 0; ks < 3; ks++) {
            int k0 = ks*16 + 2*cIdx;
            float a0 = sMSw[r0*MS_STRIDE + k0];
            float a1 = sMSw[r0*MS_STRIDE + k0 + 1];
            float b0 = sMSw[(r0+8)*MS_STRIDE + k0];
            float b1 = sMSw[(r0+8)*MS_STRIDE + k0 + 1];
            int k2 = k0 + 8;
            bool ok = (k2 < 40);
            float a2 = ok ? sMSw[r0*MS_STRIDE + k2] : 0.f;
            float a3 = ok ? sMSw[r0*MS_STRIDE + k2 + 1] : 0.f;
            float b2v = ok ? sMSw[(r0+8)*MS_STRIDE + k2] : 0.f;
            float b3v = ok ? sMSw[(r0+8)*MS_STRIDE + k2 + 1] : 0.f;
            if (ks == 2 && cIdx == 3) { a1 = 1.0f; b1 = 1.0f; }  // k=39 bias col
            ahi[ks][0] = pkbf(a1, a0);
            ahi[ks][1] = pkbf(b1, b0);
            ahi[ks][2] = pkbf(a3, a2);
            ahi[ks][3] = pkbf(b3v, b2v);
            float fe, fo;
            fe = __uint_as_float(ahi[ks][0] << 16);
            fo = __uint_as_float(ahi[ks][0] & 0xFFFF0000u);
            alo[ks][0] = pkbf(a1 - fo, a0 - fe);
            fe = __uint_as_float(ahi[ks][1] << 16);
            fo = __uint_as_float(ahi[ks][1] & 0xFFFF0000u);
            alo[ks][1] = pkbf(b1 - fo, b0 - fe);
            fe = __uint_as_float(ahi[ks][2] << 16);
            fo = __uint_as_float(ahi[ks][2] & 0xFFFF0000u);
            alo[ks][2] = pkbf(a3 - fo, a2 - fe);
            fe = __uint_as_float(ahi[ks][3] << 16);
            fo = __uint_as_float(ahi[ks][3] & 0xFFFF0000u);
            alo[ks][3] = pkbf(b3v - fo, b2v - fe);
        }

        u64 pA[8], pB[8];
        #pragma unroll
        for (int q = 0; q < 8; q++) { pA[q] = 0ULL; pB[q] = 0ULL; }

        #pragma unroll 1
        for (int half = 0; half < 2; half++) {
            float acc[8][4];
            #pragma unroll
            for (int nt = 0; nt < 8; nt++)
                #pragma unroll
                for (int i = 0; i < 4; i++) acc[nt][i] = 0.f;

            #pragma unroll
            for (int ks = 0; ks < 3; ks++) {
                #pragma unroll
                for (int nt = 0; nt < 8; nt++) {
                    float4 f = ((const float4*)sW3P)[((half*8 + nt)*3 + ks)*32 + lane];
                    u32 bhi[2] = {__float_as_uint(f.x), __float_as_uint(f.y)};
                    u32 blo[2] = {__float_as_uint(f.z), __float_as_uint(f.w)};
                    mma_bf16(acc[nt], ahi[ks], bhi);
                    mma_bf16(acc[nt], ahi[ks], blo);
                    mma_bf16(acc[nt], alo[ks], bhi);
                }
            }

            // fold x3 (this 64-col half) into mv partials
            #pragma unroll
            for (int nt = 0; nt < 8; nt++) {
                int ht = half*8 + nt;
                const ulonglong2* wp = (const ulonglong2*)(sWmvP + ((ht*4 + cIdx)*9)*4);
                float xA0 = fmaxf(acc[nt][0], 0.f);
                float xA1 = fmaxf(acc[nt][1], 0.f);
                float xB0 = fmaxf(acc[nt][2], 0.f);
                float xB1 = fmaxf(acc[nt][3], 0.f);
                u64 dA0 = f2dup(xA0), dA1 = f2dup(xA1);
                u64 dB0 = f2dup(xB0), dB1 = f2dup(xB1);
                #pragma unroll
                for (int q = 0; q < 4; q++) {
                    ulonglong2 c0v = wp[q];
                    ulonglong2 c1v = wp[4 + q];
                    pA[2*q]   = f2fma(c0v.x, dA0, pA[2*q]);
                    pA[2*q+1] = f2fma(c0v.y, dA0, pA[2*q+1]);
                    pA[2*q]   = f2fma(c1v.x, dA1, pA[2*q]);
                    pA[2*q+1] = f2fma(c1v.y, dA1, pA[2*q+1]);
                    pB[2*q]   = f2fma(c0v.x, dB0, pB[2*q]);
                    pB[2*q+1] = f2fma(c0v.y, dB0, pB[2*q+1]);
                    pB[2*q]   = f2fma(c1v.x, dB1, pB[2*q]);
                    pB[2*q+1] = f2fma(c1v.y, dB1, pB[2*q+1]);
                }
            }
        }

        #pragma unroll
        for (int q = 0; q < 8; q++) {
            pA[q] = f2add(pA[q], __shfl_xor_sync(0xffffffffu, pA[q], 1));
            pB[q] = f2add(pB[q], __shfl_xor_sync(0xffffffffu, pB[q], 1));
            pA[q] = f2add(pA[q], __shfl_xor_sync(0xffffffffu, pA[q], 2));
            pB[q] = f2add(pB[q], __shfl_xor_sync(0xffffffffu, pB[q], 2));
        }
        {
            int eA = locE0 + pass*16 + r0;
            int eB = eA + 8;
            float4 bq = *(const float4*)&sBmv[4*cIdx];
            float2 a0 = f2unpack(pA[2*cIdx]);
            float2 a1 = f2unpack(pA[2*cIdx+1]);
            float2 b0 = f2unpack(pB[2*cIdx]);
            float2 b1 = f2unpack(pB[2*cIdx+1]);
            *(float4*)&sMV[eA*20 + 4*cIdx] =
                make_float4(a0.x + bq.x, a0.y + bq.y, a1.x + bq.z, a1.y + bq.w);
            *(float4*)&sMV[eB*20 + 4*cIdx] =
                make_float4(b0.x + bq.x, b0.y + bq.y, b1.x + bq.z, b1.y + bq.w);
        }
    }
    __syncwarp();

    // ======== reparam + decoder: 1 element/thread ========
    const int b = blockIdx.x * NT + t;
    float mvs[16];
    {
        const float4* mvp = (const float4*)&sMV[t*20];
        #pragma unroll
        for (int q = 0; q < 4; q++) {
            float4 v = mvp[q];
            mvs[4*q+0] = v.x; mvs[4*q+1] = v.y; mvs[4*q+2] = v.z; mvs[4*q+3] = v.w;
        }
    }

    const float4* epv = (const float4*)(eps + (size_t)b * 8);
    float4 e0 = epv[0], e1 = epv[1];
    float ev[8] = {e0.x, e0.y, e0.z, e0.w, e1.x, e1.y, e1.z, e1.w};
    float zv[8];
    #pragma unroll
    for (int i = 0; i < 8; i++)
        zv[i] = fmaf(ev[i], __expf(0.5f * mvs[8+i]), mvs[i]);

    const float* ic = initial_c + (size_t)b * 30;
    u64 d2[12];
    d2[0] = f2pack(__ldg(&ic[0]),  __ldg(&ic[1]));
    d2[1] = f2pack(__ldg(&ic[2]),  __ldg(&ic[3]));
    d2[2] = f2pack(__ldg(&ic[10]), __ldg(&ic[11]));
    d2[3] = f2pack(__ldg(&ic[12]), __ldg(&ic[13]));
    d2[4] = f2pack(__ldg(&ic[14]), __ldg(&ic[18]));
    d2[5] = f2pack(__ldg(&ic[22]), __ldg(&ic[26]));
    d2[6] = f2pack(zv[0], zv[1]);
    d2[7] = f2pack(zv[2], zv[3]);
    d2[8] = f2pack(zv[4], zv[5]);
    d2[9] = f2pack(zv[6], zv[7]);
    d2[10] = f2pack(1.f, 0.f);
    d2[11] = 0ULL;

    u64 r2[6];
    {
        const ulonglong2* bb = (const ulonglong2*)sBd2;
        #pragma unroll
        for (int q = 0; q < 3; q++) {
            ulonglong2 v = bb[q];
            r2[2*q] = v.x; r2[2*q+1] = v.y;
        }
    }

    #pragma unroll 4
    for (int h = 0; h < 32; h++) {
        const ulonglong2* w1r = (const ulonglong2*)(sWd1 + h*24);
        u64 t0 = 0ULL, t1 = 0ULL, t2 = 0ULL, t3 = 0ULL;
        #pragma unroll
        for (int q = 0; q < 6; q += 2) {
            ulonglong2 cc0 = w1r[q];
            ulonglong2 cc1 = w1r[q+1];
            t0 = f2fma(cc0.x, d2[2*q],   t0);
            t1 = f2fma(cc0.y, d2[2*q+1], t1);
            t2 = f2fma(cc1.x, d2[2*q+2], t2);
            t3 = f2fma(cc1.y, d2[2*q+3], t3);
        }
        u64 st = f2add(f2add(t0, t2), f2add(t1, t3));
        float2 u = f2unpack(st);
        float hv = fmaxf(u.x + u.y, 0.f);
        u64 hp = f2dup(hv);
        const ulonglong2* w2r = (const ulonglong2*)(sWd2 + h*12);
        #pragma unroll
        for (int q = 0; q < 3; q++) {
            ulonglong2 c = w2r[q];
            r2[2*q]   = f2fma(c.x, hp, r2[2*q]);
            r2[2*q+1] = f2fma(c.y, hp, r2[2*q+1]);
        }
    }

    float rr[12];
    #pragma unroll
    for (int q = 0; q < 6; q++) {
        float2 v = f2unpack(r2[q]);
        rr[2*q] = v.x; rr[2*q+1] = v.y;
    }
    float* out_rec = out + (size_t)b * 12;
    #pragma unroll
    for (int ii = 0; ii < 3; ii++) {
        float4 v;
        v.x = __fdividef(1.f, 1.f + __expf(-rr[ii*4+0]));
        v.y = __fdividef(1.f, 1.f + __expf(-rr[ii*4+1]));
        v.z = __fdividef(1.f, 1.f + __expf(-rr[ii*4+2]));
        v.w = __fdividef(1.f, 1.f + __expf(-rr[ii*4+3]));
        ((float4*)out_rec)[ii] = v;
    }
    float* out_mean = out + (size_t)12*BATCH + (size_t)b*8;
    ((float4*)out_mean)[0] = make_float4(mvs[0], mvs[1], mvs[2], mvs[3]);
    ((float4*)out_mean)[1] = make_float4(mvs[4], mvs[5], mvs[6], mvs[7]);
    float* out_lv = out + (size_t)20*BATCH + (size_t)b*8;
    ((float4*)out_lv)[0] = make_float4(mvs[8],  mvs[9],  mvs[10], mvs[11]);
    ((float4*)out_lv)[1] = make_float4(mvs[12], mvs[13], mvs[14], mvs[15]);
    float* out_z = out + (size_t)28*BATCH + (size_t)b*8;
    ((float4*)out_z)[0] = make_float4(zv[0], zv[1], zv[2], zv[3]);
    ((float4*)out_z)[1] = make_float4(zv[4], zv[5], zv[6], zv[7]);
}

extern "C" void kernel_launch(void* const* d_in, const int* in_sizes, int n_in,
                              void* d_out, int out_size)
{
    const float* initial_c = (const float*)d_in[0];
    // d_in[1] = initial_s (unused)
    const float* current_c = (const float*)d_in[2];
    const float* eps       = (const float*)d_in[3];
    const float* W1  = (const float*)d_in[4];
    const float* b1  = (const float*)d_in[5];
    const float* W2  = (const float*)d_in[6];
    const float* b2  = (const float*)d_in[7];
    const float* W3  = (const float*)d_in[8];
    const float* b3  = (const float*)d_in[9];
    const float* Wm  = (const float*)d_in[10];
    const float* bm  = (const float*)d_in[11];
    const float* Wv  = (const float*)d_in[12];
    const float* bv  = (const float*)d_in[13];
    const float* Wd1 = (const float*)d_in[14];
    const float* bd1 = (const float*)d_in[15];
    const float* Wd2 = (const float*)d_in[16];
    const float* bd2 = (const float*)d_in[17];
    float* out = (float*)d_out;

    cudaFuncSetAttribute(msg_kernel, cudaFuncAttributeMaxDynamicSharedMemorySize, SMEM1_BYTES);
    cudaFuncSetAttribute(dec_kernel, cudaFuncAttributeMaxDynamicSharedMemorySize, SMEM2_BYTES);

    msg_kernel<<<BATCH / NT, NT, SMEM1_BYTES>>>(current_c, W1, b1, W2, b2);
    dec_kernel<<<BATCH / NT, NT, SMEM2_BYTES>>>(initial_c, eps,
        W3, b3, Wm, bm, Wv, bv, Wd1, bd1, Wd2, bd2, out);
}

// round 17
// speedup vs baseline: 2.5756x; 1.1887x over previous
#include <cuda_runtime.h>
#include <cuda_bf16.h>
#include <math.h>

// ContextVAE, two-kernel pipeline (R17: dec's x3 @ Wmv GEMM2 moved onto
// tensor cores via C-fragment reuse — GEMM1's output fragment IS GEMM2's
// A fragment when adjacent n-tiles pair into one k16 chunk; msg = R16):
//  K1 (msg): x1 @ W2^T via bf16 m16n8k16 (3-term).
//  K2 (dec): msum @ W3^T via bf16 m16n8k16; x3 @ Wmv via bf16 m16n8k16
//            fragment-chained (3-term); reparam + decoder scalar.

#define BATCH 262144
#define NT 256

typedef unsigned long long u64;
typedef unsigned int u32;

__device__ float g_msum[(size_t)BATCH * 40];   // 42MB scratch (row layout)

__device__ __forceinline__ u64 f2fma(u64 a, u64 b, u64 c) {
    u64 d;
    asm("fma.rn.f32x2 %0, %1, %2, %3;" : "=l"(d) : "l"(a), "l"(b), "l"(c));
    return d;
}
__device__ __forceinline__ u64 f2add(u64 a, u64 b) {
    u64 d;
    asm("add.rn.f32x2 %0, %1, %2;" : "=l"(d) : "l"(a), "l"(b));
    return d;
}
__device__ __forceinline__ u64 f2pack(float lo, float hi) {
    u64 r;
    asm("mov.b64 %0, {%1, %2};" : "=l"(r) : "f"(lo), "f"(hi));
    return r;
}
__device__ __forceinline__ u64 f2dup(float v) {
    u64 r;
    asm("mov.b64 %0, {%1, %1};" : "=l"(r) : "f"(v));
    return r;
}
__device__ __forceinline__ float2 f2unpack(u64 p) {
    float2 r;
    asm("mov.b64 {%0, %1}, %2;" : "=f"(r.x), "=f"(r.y) : "l"(p));
    return r;
}
// pack two f32 -> bf16x2; hi half = first arg, lo half = second arg.
__device__ __forceinline__ u32 pkbf(float hi, float lo) {
    u32 d;
    asm("cvt.rn.bf16x2.f32 %0, %1, %2;" : "=r"(d) : "f"(hi), "f"(lo));
    return d;
}
__device__ __forceinline__ void mma_bf16(float* d, const u32* a, const u32* b) {
    asm("mma.sync.aligned.m16n8k16.row.col.f32.bf16.bf16.f32 "
        "{%0,%1,%2,%3}, {%4,%5,%6,%7}, {%8,%9}, {%0,%1,%2,%3};"
        : "+f"(d[0]), "+f"(d[1]), "+f"(d[2]), "+f"(d[3])
        : "r"(a[0]), "r"(a[1]), "r"(a[2]), "r"(a[3]), "r"(b[0]), "r"(b[1]));
}

// ===================== K1: message stage (bf16 m16n8k16, = R16) ===============
#define OFF1_W1W  0
#define OFF1_W1B  (OFF1_W1W + 128*4)
#define OFF1_W2P  (OFF1_W1B + 128*4)
#define OFF1_B2   (OFF1_W2P + 8*5*32*4)
#define OFF1_CUR  (OFF1_B2 + 40)
#define SMEM1_FLOATS (OFF1_CUR + 256*12)
#define SMEM1_BYTES  (SMEM1_FLOATS * 4)

__global__ __launch_bounds__(NT, 2)
void msg_kernel(const float* __restrict__ current_c,
                const float* __restrict__ W1, const float* __restrict__ b1,
                const float* __restrict__ W2, const float* __restrict__ b2)
{
    extern __shared__ float sm[];
    float* sW1w = sm + OFF1_W1W;
    float* sW1b = sm + OFF1_W1B;
    float* sW2P = sm + OFF1_W2P;
    float* sB2  = sm + OFF1_B2;
    float* sCur = sm + OFF1_CUR;

    const int t = threadIdx.x;

    for (int o = t; o < 128; o += NT) {
        sW1w[o*4+0] = __ldg(&W1[o*13 + 10]);
        sW1w[o*4+1] = __ldg(&W1[o*13 + 11]);
        sW1w[o*4+2] = __ldg(&W1[o*13 + 12]);
        sW1w[o*4+3] = 0.f;
        float bb = __ldg(&b1[o]) + __ldg(&W1[o*13 + 0]);
        #pragma unroll
        for (int e = 0; e < 4; e++)
            sW1b[o*4+e] = bb + __ldg(&W1[o*13 + 6 + e]);
    }
    for (int i = t; i < 8*5*32; i += NT) {
        int ks = i / 160;
        int r  = i % 160;
        int nt = r / 32;
        int lane = r % 32;
        int rr = lane >> 2, cI = lane & 3;
        int n  = nt*8 + rr;
        int K0 = ks*16;
        float w0 = (n < 39) ? __ldg(&W2[n*128 + K0 + 2*cI])     : 0.f;
        float w1 = (n < 39) ? __ldg(&W2[n*128 + K0 + 2*cI + 1]) : 0.f;
        float w2 = (n < 39) ? __ldg(&W2[n*128 + K0 + 2*cI + 8]) : 0.f;
        float w3 = (n < 39) ? __ldg(&W2[n*128 + K0 + 2*cI + 9]) : 0.f;
        u32 hi01 = pkbf(w1, w0);
        u32 hi23 = pkbf(w3, w2);
        float f0 = __uint_as_float(hi01 << 16);
        float f1 = __uint_as_float(hi01 & 0xFFFF0000u);
        float f2 = __uint_as_float(hi23 << 16);
        float f3 = __uint_as_float(hi23 & 0xFFFF0000u);
        u32 lo01 = pkbf(w1 - f1, w0 - f0);
        u32 lo23 = pkbf(w3 - f3, w2 - f2);
        float4 pk4;
        pk4.x = __uint_as_float(hi01);
        pk4.y = __uint_as_float(hi23);
        pk4.z = __uint_as_float(lo01);
        pk4.w = __uint_as_float(lo23);
        ((float4*)sW2P)[i] = pk4;
    }
    if (t < 40) sB2[t] = (t < 39) ? __ldg(&b2[t]) : 0.f;
    {
        const int b = blockIdx.x * NT + t;
        const float* cc = current_c + (size_t)b * 30;
        #pragma unroll
        for (int e = 0; e < 4; e++) {
            sCur[t*12 + 3*e + 0] = __ldg(&cc[e]);
            sCur[t*12 + 3*e + 1] = __ldg(&cc[10 + e]);
            sCur[t*12 + 3*e + 2] = __ldg(&cc[14 + 4*e]);
        }
    }
    __syncthreads();

    const int lane = t & 31;
    const int warp = t >> 5;
    const int r0   = lane >> 2;
    const int cIdx = lane & 3;
    const int edge = r0 & 3;
    const int blockElem0 = blockIdx.x * NT;

    #pragma unroll 1
    for (int pass = 0; pass < 4; pass++) {
        const int eb = warp*32 + pass*8;

        float p[2][2][3];
        #pragma unroll
        for (int mt = 0; mt < 2; mt++)
            #pragma unroll
            for (int h = 0; h < 2; h++) {
                int e = eb + mt*4 + (r0 >> 2) + 2*h;
                p[mt][h][0] = sCur[e*12 + edge*3 + 0];
                p[mt][h][1] = sCur[e*12 + edge*3 + 1];
                p[mt][h][2] = sCur[e*12 + edge*3 + 2];
            }

        float acc[2][5][4];
        #pragma unroll
        for (int mt = 0; mt < 2; mt++)
            #pragma unroll
            for (int nt = 0; nt < 5; nt++)
                #pragma unroll
                for (int i = 0; i < 4; i++) acc[mt][nt][i] = 0.f;

        #pragma unroll 1
        for (int ks = 0; ks < 8; ks++) {
            const int ke0 = ks*16 + 2*cIdx;
            float4 wE0 = ((const float4*)sW1w)[ke0];
            float4 wO0 = ((const float4*)sW1w)[ke0 + 1];
            float4 wE1 = ((const float4*)sW1w)[ke0 + 8];
            float4 wO1 = ((const float4*)sW1w)[ke0 + 9];
            float bE0 = sW1b[(ke0)*4 + edge];
            float bO0 = sW1b[(ke0+1)*4 + edge];
            float bE1 = sW1b[(ke0+8)*4 + edge];
            float bO1 = sW1b[(ke0+9)*4 + edge];

            u32 bhi[5][2], blo[5][2];
            #pragma unroll
            for (int nt = 0; nt < 5; nt++) {
                float4 f = ((const float4*)sW2P)[(ks*5 + nt)*32 + lane];
                bhi[nt][0] = __float_as_uint(f.x);
                bhi[nt][1] = __float_as_uint(f.y);
                blo[nt][0] = __float_as_uint(f.z);
                blo[nt][1] = __float_as_uint(f.w);
            }

            #pragma unroll
            for (int mt = 0; mt < 2; mt++) {
                float xE0[2], xO0[2], xE1[2], xO1[2];
                #pragma unroll
                for (int h = 0; h < 2; h++) {
                    const float q0 = p[mt][h][0], q1 = p[mt][h][1], q2 = p[mt][h][2];
                    xE0[h] = fmaxf(fmaf(wE0.x, q0, fmaf(wE0.y, q1, fmaf(wE0.z, q2, bE0))), 0.f);
                    xO0[h] = fmaxf(fmaf(wO0.x, q0, fmaf(wO0.y, q1, fmaf(wO0.z, q2, bO0))), 0.f);
                    xE1[h] = fmaxf(fmaf(wE1.x, q0, fmaf(wE1.y, q1, fmaf(wE1.z, q2, bE1))), 0.f);
                    xO1[h] = fmaxf(fmaf(wO1.x, q0, fmaf(wO1.y, q1, fmaf(wO1.z, q2, bO1))), 0.f);
                }
                u32 ahi[4], alo[4];
                ahi[0] = pkbf(xO0[0], xE0[0]);
                ahi[1] = pkbf(xO0[1], xE0[1]);
                ahi[2] = pkbf(xO1[0], xE1[0]);
                ahi[3] = pkbf(xO1[1], xE1[1]);
                {
                    float fe, fo;
                    fe = __uint_as_float(ahi[0] << 16);
                    fo = __uint_as_float(ahi[0] & 0xFFFF0000u);
                    alo[0] = pkbf(xO0[0] - fo, xE0[0] - fe);
                    fe = __uint_as_float(ahi[1] << 16);
                    fo = __uint_as_float(ahi[1] & 0xFFFF0000u);
                    alo[1] = pkbf(xO0[1] - fo, xE0[1] - fe);
                    fe = __uint_as_float(ahi[2] << 16);
                    fo = __uint_as_float(ahi[2] & 0xFFFF0000u);
                    alo[2] = pkbf(xO1[0] - fo, xE1[0] - fe);
                    fe = __uint_as_float(ahi[3] << 16);
                    fo = __uint_as_float(ahi[3] & 0xFFFF0000u);
                    alo[3] = pkbf(xO1[1] - fo, xE1[1] - fe);
                }
                #pragma unroll
                for (int nt = 0; nt < 5; nt++) {
                    mma_bf16(acc[mt][nt], ahi, bhi[nt]);
                    mma_bf16(acc[mt][nt], ahi, blo[nt]);
                    mma_bf16(acc[mt][nt], alo, bhi[nt]);
                }
            }
        }

        #pragma unroll
        for (int mt = 0; mt < 2; mt++) {
            #pragma unroll
            for (int nt = 0; nt < 5; nt++) {
                int jb = nt*8 + cIdx*2;
                float2 b2v = *(const float2*)&sB2[jb];
                float v0 = fmaxf(acc[mt][nt][0] + b2v.x, 0.f);
                float v1 = fmaxf(acc[mt][nt][1] + b2v.y, 0.f);
                float v2 = fmaxf(acc[mt][nt][2] + b2v.x, 0.f);
                float v3 = fmaxf(acc[mt][nt][3] + b2v.y, 0.f);
                v0 += __shfl_xor_sync(0xffffffffu, v0, 4);
                v1 += __shfl_xor_sync(0xffffffffu, v1, 4);
                v2 += __shfl_xor_sync(0xffffffffu, v2, 4);
                v3 += __shfl_xor_sync(0xffffffffu, v3, 4);
                v0 += __shfl_xor_sync(0xffffffffu, v0, 8);
                v1 += __shfl_xor_sync(0xffffffffu, v1, 8);
                v2 += __shfl_xor_sync(0xffffffffu, v2, 8);
                v3 += __shfl_xor_sync(0xffffffffu, v3, 8);
                if (edge == 0) {
                    int eLo = blockElem0 + eb + mt*4 + (r0 >> 2);
                    *(float2*)&g_msum[(size_t)eLo*40 + jb]     = make_float2(v0, v1);
                    *(float2*)&g_msum[(size_t)(eLo+2)*40 + jb] = make_float2(v2, v3);
                }
            }
        }
    }
}

// ===================== K2: readout (bf16) + GEMM2-on-mma + decoder ============
// sW3P:  float4 idx (ntG*3+ks)*32+lane  (as R16)
// sWmv2: float4 idx (ksg*2+ntile)*32+lane = {bhi01, bhi23, blo01, blo23}
//   n = ntile*8 + (lane>>2); val(n, j) = (n<8 ? Wm[n][j] : Wv[n-8][j]);
//   j pairs (ksg*16+2c, +1) and (+8, +9).
#define OFF2_W3P  0
#define OFF2_WMV2 (OFF2_W3P + 16*3*32*4)      // 6144
#define OFF2_WD1  (OFF2_WMV2 + 8*2*32*4)      // 8192
#define OFF2_WD2  (OFF2_WD1 + 32*24)          // 8960
#define OFF2_BMV  (OFF2_WD2 + 32*12)          // 9344
#define OFF2_BD2  (OFF2_BMV + 16)             // 9360
#define OFF2_MV   (OFF2_BD2 + 16)             // 9376, 16B aligned
#define OFF2_MS   (OFF2_MV + 256*20)          // 14496
#define MS_STRIDE 44
#define SMEM2_FLOATS (OFF2_MS + 8*16*MS_STRIDE)
#define SMEM2_BYTES  (SMEM2_FLOATS * 4)

__global__ __launch_bounds__(NT, 2)
void dec_kernel(const float* __restrict__ initial_c,
                const float* __restrict__ eps,
                const float* __restrict__ W3, const float* __restrict__ b3,
                const float* __restrict__ Wm, const float* __restrict__ bm,
                const float* __restrict__ Wv, const float* __restrict__ bv,
                const float* __restrict__ Wd1, const float* __restrict__ bd1,
                const float* __restrict__ Wd2, const float* __restrict__ bd2,
                float* __restrict__ out)
{
    extern __shared__ float sm[];
    float* sW3P  = sm + OFF2_W3P;
    float* sWmv2 = sm + OFF2_WMV2;
    float* sWd1  = sm + OFF2_WD1;
    float* sWd2  = sm + OFF2_WD2;
    float* sBmv  = sm + OFF2_BMV;
    float* sBd2  = sm + OFF2_BD2;
    float* sMV   = sm + OFF2_MV;

    const int t = threadIdx.x;

    // bf16 fragment-packed W3 (+ b3 at k=39, 0 beyond) — as R16
    for (int i = t; i < 16*3*32; i += NT) {
        int ntG = i / 96;
        int r   = i % 96;
        int ks  = r / 32;
        int ln  = r % 32;
        int rr0 = ln >> 2, cI = ln & 3;
        int n  = ntG*8 + rr0;
        int K0 = ks*16;
        int ka = K0 + 2*cI, kb = ka + 1, kc = ka + 8, kd = kc + 1;
        float w0 = (ka < 39) ? __ldg(&W3[n*39 + ka]) : ((ka == 39) ? __ldg(&b3[n]) : 0.f);
        float w1 = (kb < 39) ? __ldg(&W3[n*39 + kb]) : ((kb == 39) ? __ldg(&b3[n]) : 0.f);
        float w2 = (kc < 39) ? __ldg(&W3[n*39 + kc]) : ((kc == 39) ? __ldg(&b3[n]) : 0.f);
        float w3v = (kd < 39) ? __ldg(&W3[n*39 + kd]) : ((kd == 39) ? __ldg(&b3[n]) : 0.f);
        u32 hi01 = pkbf(w1, w0);
        u32 hi23 = pkbf(w3v, w2);
        float f0 = __uint_as_float(hi01 << 16);
        float f1 = __uint_as_float(hi01 & 0xFFFF0000u);
        float f2 = __uint_as_float(hi23 << 16);
        float f3 = __uint_as_float(hi23 & 0xFFFF0000u);
        u32 lo01 = pkbf(w1 - f1, w0 - f0);
        u32 lo23 = pkbf(w3v - f3, w2 - f2);
        float4 pk4;
        pk4.x = __uint_as_float(hi01);
        pk4.y = __uint_as_float(hi23);
        pk4.z = __uint_as_float(lo01);
        pk4.w = __uint_as_float(lo23);
        ((float4*)sW3P)[i] = pk4;
    }
    // bf16 fragment-packed Wmv for GEMM2 (k = x3 column j, n = mv output)
    for (int i = t; i < 8*2*32; i += NT) {
        int ksg   = i / 64;
        int rr    = i % 64;
        int ntile = rr / 32;
        int ln    = rr % 32;
        int rr0 = ln >> 2, cI = ln & 3;
        int n  = ntile*8 + rr0;          // 0..15 (0-7 Wm, 8-15 Wv)
        int j0 = ksg*16 + 2*cI;
        const float* Wn = (n < 8) ? (Wm + n*128) : (Wv + (n-8)*128);
        float w0 = __ldg(&Wn[j0]);
        float w1 = __ldg(&Wn[j0 + 1]);
        float w2 = __ldg(&Wn[j0 + 8]);
        float w3v = __ldg(&Wn[j0 + 9]);
        u32 hi01 = pkbf(w1, w0);
        u32 hi23 = pkbf(w3v, w2);
        float f0 = __uint_as_float(hi01 << 16);
        float f1 = __uint_as_float(hi01 & 0xFFFF0000u);
        float f2 = __uint_as_float(hi23 << 16);
        float f3 = __uint_as_float(hi23 & 0xFFFF0000u);
        u32 lo01 = pkbf(w1 - f1, w0 - f0);
        u32 lo23 = pkbf(w3v - f3, w2 - f2);
        float4 pk4;
        pk4.x = __uint_as_float(hi01);
        pk4.y = __uint_as_float(hi23);
        pk4.z = __uint_as_float(lo01);
        pk4.w = __uint_as_float(lo23);
        ((float4*)sWmv2)[i] = pk4;
    }
    for (int i = t; i < 32*24; i += NT) {
        int h = i / 24, q = i % 24;
        float v;
        if (q < 12)       v = __ldg(&Wd1[h*25 + 5 + q]);
        else if (q < 20)  v = __ldg(&Wd1[h*25 + 17 + (q-12)]);
        else if (q == 20) v = __ldg(&bd1[h]) + __ldg(&Wd1[h*25 + 0]);
        else              v = 0.f;
        sWd1[i] = v;
    }
    for (int i = t; i < 32*12; i += NT) {
        int h = i / 12, j = i % 12;
        sWd2[i] = __ldg(&Wd2[j*32 + h]);
    }
    if (t < 16) sBmv[t] = (t < 8) ? __ldg(&bm[t]) : __ldg(&bv[t-8]);
    if (t < 12) sBd2[t] = __ldg(&bd2[t]);
    __syncthreads();

    const int lane = t & 31;
    const int warp = t >> 5;
    const int r0   = lane >> 2;
    const int cIdx = lane & 3;
    const int warpE0 = blockIdx.x * NT + warp*32;
    const int locE0  = warp*32;
    float* sMSw = sm + OFF2_MS + warp * 16 * MS_STRIDE;

    #pragma unroll 1
    for (int pass = 0; pass < 2; pass++) {
        __syncwarp();
        {
            const float4* src = (const float4*)(g_msum + (size_t)(warpE0 + pass*16) * 40);
            #pragma unroll
            for (int it = 0; it < 5; it++) {
                int idx = it*32 + lane;
                float4 v = __ldg(&src[idx]);
                int e = idx / 10, c = idx % 10;
                *(float4*)&sMSw[e*MS_STRIDE + c*4] = v;
            }
        }
        __syncwarp();

        // A fragments for GEMM1 (bf16 k16), computed once per pass
        u32 ahi1[3][4], alo1[3][4];
        #pragma unroll
        for (int ks = 0; ks < 3; ks++) {
            int k0 = ks*16 + 2*cIdx;
            float a0 = sMSw[r0*MS_STRIDE + k0];
            float a1 = sMSw[r0*MS_STRIDE + k0 + 1];
            float b0 = sMSw[(r0+8)*MS_STRIDE + k0];
            float b1 = sMSw[(r0+8)*MS_STRIDE + k0 + 1];
            int k2 = k0 + 8;
            bool ok = (k2 < 40);
            float a2 = ok ? sMSw[r0*MS_STRIDE + k2] : 0.f;
            float a3 = ok ? sMSw[r0*MS_STRIDE + k2 + 1] : 0.f;
            float b2v = ok ? sMSw[(r0+8)*MS_STRIDE + k2] : 0.f;
            float b3v = ok ? sMSw[(r0+8)*MS_STRIDE + k2 + 1] : 0.f;
            if (ks == 2 && cIdx == 3) { a1 = 1.0f; b1 = 1.0f; }  // k=39 bias col
            ahi1[ks][0] = pkbf(a1, a0);
            ahi1[ks][1] = pkbf(b1, b0);
            ahi1[ks][2] = pkbf(a3, a2);
            ahi1[ks][3] = pkbf(b3v, b2v);
            float fe, fo;
            fe = __uint_as_float(ahi1[ks][0] << 16);
            fo = __uint_as_float(ahi1[ks][0] & 0xFFFF0000u);
            alo1[ks][0] = pkbf(a1 - fo, a0 - fe);
            fe = __uint_as_float(ahi1[ks][1] << 16);
            fo = __uint_as_float(ahi1[ks][1] & 0xFFFF0000u);
            alo1[ks][1] = pkbf(b1 - fo, b0 - fe);
            fe = __uint_as_float(ahi1[ks][2] << 16);
            fo = __uint_as_float(ahi1[ks][2] & 0xFFFF0000u);
            alo1[ks][2] = pkbf(a3 - fo, a2 - fe);
            fe = __uint_as_float(ahi1[ks][3] << 16);
            fo = __uint_as_float(ahi1[ks][3] & 0xFFFF0000u);
            alo1[ks][3] = pkbf(b3v - fo, b2v - fe);
        }

        float mvacc[2][4];
        #pragma unroll
        for (int nt2 = 0; nt2 < 2; nt2++)
            #pragma unroll
            for (int i = 0; i < 4; i++) mvacc[nt2][i] = 0.f;

        #pragma unroll 1
        for (int half = 0; half < 2; half++) {
            float acc[8][4];
            #pragma unroll
            for (int nt = 0; nt < 8; nt++)
                #pragma unroll
                for (int i = 0; i < 4; i++) acc[nt][i] = 0.f;

            #pragma unroll
            for (int ks = 0; ks < 3; ks++) {
                #pragma unroll
                for (int nt = 0; nt < 8; nt++) {
                    float4 f = ((const float4*)sW3P)[((half*8 + nt)*3 + ks)*32 + lane];
                    u32 bhi[2] = {__float_as_uint(f.x), __float_as_uint(f.y)};
                    u32 blo[2] = {__float_as_uint(f.z), __float_as_uint(f.w)};
                    mma_bf16(acc[nt], ahi1[ks], bhi);
                    mma_bf16(acc[nt], ahi1[ks], blo);
                    mma_bf16(acc[nt], alo1[ks], bhi);
                }
            }

            // GEMM2: relu(acc) fragments chain directly into mv mma
            #pragma unroll
            for (int kp = 0; kp < 4; kp++) {
                const int nt0 = 2*kp, nt1 = nt0 + 1;
                float xa0 = fmaxf(acc[nt0][0], 0.f), xa1 = fmaxf(acc[nt0][1], 0.f);
                float xb0 = fmaxf(acc[nt0][2], 0.f), xb1 = fmaxf(acc[nt0][3], 0.f);
                float xc0 = fmaxf(acc[nt1][0], 0.f), xc1 = fmaxf(acc[nt1][1], 0.f);
                float xd0 = fmaxf(acc[nt1][2], 0.f), xd1 = fmaxf(acc[nt1][3], 0.f);
                u32 ahi[4], alo[4];
                ahi[0] = pkbf(xa1, xa0);
                ahi[1] = pkbf(xb1, xb0);
                ahi[2] = pkbf(xc1, xc0);
                ahi[3] = pkbf(xd1, xd0);
                float fe, fo;
                fe = __uint_as_float(ahi[0] << 16);
                fo = __uint_as_float(ahi[0] & 0xFFFF0000u);
                alo[0] = pkbf(xa1 - fo, xa0 - fe);
                fe = __uint_as_float(ahi[1] << 16);
                fo = __uint_as_float(ahi[1] & 0xFFFF0000u);
                alo[1] = pkbf(xb1 - fo, xb0 - fe);
                fe = __uint_as_float(ahi[2] << 16);
                fo = __uint_as_float(ahi[2] & 0xFFFF0000u);
                alo[2] = pkbf(xc1 - fo, xc0 - fe);
                fe = __uint_as_float(ahi[3] << 16);
                fo = __uint_as_float(ahi[3] & 0xFFFF0000u);
                alo[3] = pkbf(xd1 - fo, xd0 - fe);
                const int ksg = half*4 + kp;
                #pragma unroll
                for (int nt2 = 0; nt2 < 2; nt2++) {
                    float4 f = ((const float4*)sWmv2)[(ksg*2 + nt2)*32 + lane];
                    u32 bhi[2] = {__float_as_uint(f.x), __float_as_uint(f.y)};
                    u32 blo[2] = {__float_as_uint(f.z), __float_as_uint(f.w)};
                    mma_bf16(mvacc[nt2], ahi, bhi);
                    mma_bf16(mvacc[nt2], ahi, blo);
                    mma_bf16(mvacc[nt2], alo, bhi);
                }
            }
        }

        // write mv (+bias) to sMV — C fragment already in (elem, mv-col) layout
        {
            int eA = locE0 + pass*16 + r0;
            int eB = eA + 8;
            float2 bq0 = *(const float2*)&sBmv[2*cIdx];
            float2 bq1 = *(const float2*)&sBmv[8 + 2*cIdx];
            *(float2*)&sMV[eA*20 + 2*cIdx] =
                make_float2(mvacc[0][0] + bq0.x, mvacc[0][1] + bq0.y);
            *(float2*)&sMV[eB*20 + 2*cIdx] =
                make_float2(mvacc[0][2] + bq0.x, mvacc[0][3] + bq0.y);
            *(float2*)&sMV[eA*20 + 8 + 2*cIdx] =
                make_float2(mvacc[1][0] + bq1.x, mvacc[1][1] + bq1.y);
            *(float2*)&sMV[eB*20 + 8 + 2*cIdx] =
                make_float2(mvacc[1][2] + bq1.x, mvacc[1][3] + bq1.y);
        }
    }
    __syncwarp();

    // ======== reparam + decoder: 1 element/thread ========
    const int b = blockIdx.x * NT + t;
    float mvs[16];
    {
        const float4* mvp = (const float4*)&sMV[t*20];
        #pragma unroll
        for (int q = 0; q < 4; q++) {
            float4 v = mvp[q];
            mvs[4*q+0] = v.x; mvs[4*q+1] = v.y; mvs[4*q+2] = v.z; mvs[4*q+3] = v.w;
        }
    }

    const float4* epv = (const float4*)(eps + (size_t)b * 8);
    float4 e0 = epv[0], e1 = epv[1];
    float ev[8] = {e0.x, e0.y, e0.z, e0.w, e1.x, e1.y, e1.z, e1.w};
    float zv[8];
    #pragma unroll
    for (int i = 0; i < 8; i++)
        zv[i] = fmaf(ev[i], __expf(0.5f * mvs[8+i]), mvs[i]);

    const float* ic = initial_c + (size_t)b * 30;
    u64 d2[12];
    d2[0] = f2pack(__ldg(&ic[0]),  __ldg(&ic[1]));
    d2[1] = f2pack(__ldg(&ic[2]),  __ldg(&ic[3]));
    d2[2] = f2pack(__ldg(&ic[10]), __ldg(&ic[11]));
    d2[3] = f2pack(__ldg(&ic[12]), __ldg(&ic[13]));
    d2[4] = f2pack(__ldg(&ic[14]), __ldg(&ic[18]));
    d2[5] = f2pack(__ldg(&ic[22]), __ldg(&ic[26]));
    d2[6] = f2pack(zv[0], zv[1]);
    d2[7] = f2pack(zv[2], zv[3]);
    d2[8] = f2pack(zv[4], zv[5]);
    d2[9] = f2pack(zv[6], zv[7]);
    d2[10] = f2pack(1.f, 0.f);
    d2[11] = 0ULL;

    u64 r2[6];
    {
        const ulonglong2* bb = (const ulonglong2*)sBd2;
        #pragma unroll
        for (int q = 0; q < 3; q++) {
            ulonglong2 v = bb[q];
            r2[2*q] = v.x; r2[2*q+1] = v.y;
        }
    }

    #pragma unroll 4
    for (int h = 0; h < 32; h++) {
        const ulonglong2* w1r = (const ulonglong2*)(sWd1 + h*24);
        u64 t0 = 0ULL, t1 = 0ULL, t2 = 0ULL, t3 = 0ULL;
        #pragma unroll
        for (int q = 0; q < 6; q += 2) {
            ulonglong2 cc0 = w1r[q];
            ulonglong2 cc1 = w1r[q+1];
            t0 = f2fma(cc0.x, d2[2*q],   t0);
            t1 = f2fma(cc0.y, d2[2*q+1], t1);
            t2 = f2fma(cc1.x, d2[2*q+2], t2);
            t3 = f2fma(cc1.y, d2[2*q+3], t3);
        }
        u64 st = f2add(f2add(t0, t2), f2add(t1, t3));
        float2 u = f2unpack(st);
        float hv = fmaxf(u.x + u.y, 0.f);
        u64 hp = f2dup(hv);
        const ulonglong2* w2r = (const ulonglong2*)(sWd2 + h*12);
        #pragma unroll
        for (int q = 0; q < 3; q++) {
            ulonglong2 c = w2r[q];
            r2[2*q]   = f2fma(c.x, hp, r2[2*q]);
            r2[2*q+1] = f2fma(c.y, hp, r2[2*q+1]);
        }
    }

    float rr[12];
    #pragma unroll
    for (int q = 0; q < 6; q++) {
        float2 v = f2unpack(r2[q]);
        rr[2*q] = v.x; rr[2*q+1] = v.y;
    }
    float* out_rec = out + (size_t)b * 12;
    #pragma unroll
    for (int ii = 0; ii < 3; ii++) {
        float4 v;
        v.x = __fdividef(1.f, 1.f + __expf(-rr[ii*4+0]));
        v.y = __fdividef(1.f, 1.f + __expf(-rr[ii*4+1]));
        v.z = __fdividef(1.f, 1.f + __expf(-rr[ii*4+2]));
        v.w = __fdividef(1.f, 1.f + __expf(-rr[ii*4+3]));
        ((float4*)out_rec)[ii] = v;
    }
    float* out_mean = out + (size_t)12*BATCH + (size_t)b*8;
    ((float4*)out_mean)[0] = make_float4(mvs[0], mvs[1], mvs[2], mvs[3]);
    ((float4*)out_mean)[1] = make_float4(mvs[4], mvs[5], mvs[6], mvs[7]);
    float* out_lv = out + (size_t)20*BATCH + (size_t)b*8;
    ((float4*)out_lv)[0] = make_float4(mvs[8],  mvs[9],  mvs[10], mvs[11]);
    ((float4*)out_lv)[1] = make_float4(mvs[12], mvs[13], mvs[14], mvs[15]);
    float* out_z = out + (size_t)28*BATCH + (size_t)b*8;
    ((float4*)out_z)[0] = make_float4(zv[0], zv[1], zv[2], zv[3]);
    ((float4*)out_z)[1] = make_float4(zv[4], zv[5], zv[6], zv[7]);
}

extern "C" void kernel_launch(void* const* d_in, const int* in_sizes, int n_in,
                              void* d_out, int out_size)
{
    const float* initial_c = (const float*)d_in[0];
    // d_in[1] = initial_s (unused)
    const float* current_c = (const float*)d_in[2];
    const float* eps       = (const float*)d_in[3];
    const float* W1  = (const float*)d_in[4];
    const float* b1  = (const float*)d_in[5];
    const float* W2  = (const float*)d_in[6];
    const float* b2  = (const float*)d_in[7];
    const float* W3  = (const float*)d_in[8];
    const float* b3  = (const float*)d_in[9];
    const float* Wm  = (const float*)d_in[10];
    const float* bm  = (const float*)d_in[11];
    const float* Wv  = (const float*)d_in[12];
    const float* bv  = (const float*)d_in[13];
    const float* Wd1 = (const float*)d_in[14];
    const float* bd1 = (const float*)d_in[15];
    const float* Wd2 = (const float*)d_in[16];
    const float* bd2 = (const float*)d_in[17];
    float* out = (float*)d_out;

    cudaFuncSetAttribute(msg_kernel, cudaFuncAttributeMaxDynamicSharedMemorySize, SMEM1_BYTES);
    cudaFuncSetAttribute(dec_kernel, cudaFuncAttributeMaxDynamicSharedMemorySize, SMEM2_BYTES);

    msg_kernel<<<BATCH / NT, NT, SMEM1_BYTES>>>(current_c, W1, b1, W2, b2);
    dec_kernel<<<BATCH / NT, NT, SMEM2_BYTES>>>(initial_c, eps,
        W3, b3, Wm, bm, Wv, bv, Wd1, bd1, Wd2, bd2, out);
}